// round 1
// baseline (speedup 1.0000x reference)
#include <cuda_runtime.h>

#define BHN 128
#define LN  512
#define DN  128
#define LQN 64
#define INV_SQRT_D 0.08838834764831843f

#define BM 128
#define BN 128
#define BK 16

// Packed fp32x2 FMA (sm_100+): two independent fp32 FMAs per instruction.
#define FFMA2(d,a,b,c) asm("fma.rn.f32x2 %0, %1, %2, %3;" : "=l"(d) : "l"(a), "l"(b), "l"(c))
#define PACK2(d,x)     asm("mov.b64 %0, {%1, %1};" : "=l"(d) : "r"(__float_as_uint(x)))

__device__ __forceinline__ float2 u2f2(unsigned long long u) {
    float2 f;
    asm("mov.b64 {%0, %1}, %2;" : "=f"(f.x), "=f"(f.y) : "l"(u));
    return f;
}

// ---------------------------------------------------------------------------
// Kernel 1: raw logits S[b,q,k] = dot(Q[b,q,:], K[b,k,:])   (batched NT sgemm)
// ---------------------------------------------------------------------------
__global__ __launch_bounds__(256) void qk_kernel(const float* __restrict__ Q,
                                                 const float* __restrict__ Km,
                                                 float* __restrict__ S)
{
    __shared__ float As[BK][BM + 4];
    __shared__ float Bs[BK][BN + 4];

    const int b   = blockIdx.z;
    const int tid = threadIdx.x;
    const float* Ag = Q  + ((size_t)b * LN + blockIdx.y * BM) * DN;
    const float* Bg = Km + ((size_t)b * LN + blockIdx.x * BN) * DN;

    const int m0 = (tid >> 4) << 2;   // rows m0..m0+3 and m0+64..m0+67
    const int n0 = (tid & 15) << 2;   // cols n0..n0+3 and n0+64..n0+67

    unsigned long long acc[8][4];
    #pragma unroll
    for (int i = 0; i < 8; i++)
        #pragma unroll
        for (int j = 0; j < 4; j++) acc[i][j] = 0ull;

    for (int kb = 0; kb < DN; kb += BK) {
        #pragma unroll
        for (int i = 0; i < 2; i++) {
            int idx = tid + i * 256;
            int r = idx >> 2;
            int c = (idx & 3) << 2;
            float4 va = *(const float4*)(Ag + r * DN + kb + c);
            As[c + 0][r] = va.x; As[c + 1][r] = va.y;
            As[c + 2][r] = va.z; As[c + 3][r] = va.w;
            float4 vb = *(const float4*)(Bg + r * DN + kb + c);
            Bs[c + 0][r] = vb.x; Bs[c + 1][r] = vb.y;
            Bs[c + 2][r] = vb.z; Bs[c + 3][r] = vb.w;
        }
        __syncthreads();

        #pragma unroll
        for (int k = 0; k < BK; k++) {
            float4 a0 = *(const float4*)&As[k][m0];
            float4 a1 = *(const float4*)&As[k][m0 + 64];
            ulonglong2 b0 = *(const ulonglong2*)&Bs[k][n0];
            ulonglong2 b1 = *(const ulonglong2*)&Bs[k][n0 + 64];
            unsigned long long ap;
#define QK_ROW(i, av) do { PACK2(ap, av);                         \
            FFMA2(acc[i][0], ap, b0.x, acc[i][0]);                \
            FFMA2(acc[i][1], ap, b0.y, acc[i][1]);                \
            FFMA2(acc[i][2], ap, b1.x, acc[i][2]);                \
            FFMA2(acc[i][3], ap, b1.y, acc[i][3]); } while (0)
            QK_ROW(0, a0.x); QK_ROW(1, a0.y); QK_ROW(2, a0.z); QK_ROW(3, a0.w);
            QK_ROW(4, a1.x); QK_ROW(5, a1.y); QK_ROW(6, a1.z); QK_ROW(7, a1.w);
#undef QK_ROW
        }
        __syncthreads();
    }

    float* Cg = S + ((size_t)b * LN + blockIdx.y * BM) * LN + blockIdx.x * BN;
    #pragma unroll
    for (int mi = 0; mi < 8; mi++) {
        int m = (mi < 4) ? (m0 + mi) : (m0 + 60 + mi);
        float2 f0 = u2f2(acc[mi][0]);
        float2 f1 = u2f2(acc[mi][1]);
        float2 f2 = u2f2(acc[mi][2]);
        float2 f3 = u2f2(acc[mi][3]);
        *(float4*)(Cg + (size_t)m * LN + n0)      = make_float4(f0.x, f0.y, f1.x, f1.y);
        *(float4*)(Cg + (size_t)m * LN + n0 + 64) = make_float4(f2.x, f2.y, f3.x, f3.y);
    }
}

// ---------------------------------------------------------------------------
// Kernel 2: S[b, 448+q', 448+k'] += dot(question_rel[b,q',k',:], Q[b,448+q',:])
// One warp per (q',k') dot; one block per (b,q').
// ---------------------------------------------------------------------------
__global__ __launch_bounds__(256) void rel_kernel(const float* __restrict__ Q,
                                                  const float* __restrict__ R,
                                                  float* __restrict__ S)
{
    __shared__ float qrow[DN];
    const int b  = blockIdx.x >> 6;
    const int qp = blockIdx.x & 63;
    const int tid = threadIdx.x;

    if (tid < 32)
        ((float4*)qrow)[tid] =
            *(const float4*)(Q + ((size_t)b * LN + (LN - LQN) + qp) * DN + tid * 4);
    __syncthreads();

    const int w = tid >> 5, lane = tid & 31;
    const float4 qv = ((const float4*)qrow)[lane];

    #pragma unroll
    for (int i = 0; i < 8; i++) {
        int kp = w + i * 8;
        const float4* rp =
            (const float4*)(R + (((size_t)b * LQN + qp) * LQN + kp) * DN);
        float4 rv = rp[lane];
        float s = rv.x * qv.x + rv.y * qv.y + rv.z * qv.z + rv.w * qv.w;
        #pragma unroll
        for (int o = 16; o; o >>= 1) s += __shfl_xor_sync(0xffffffffu, s, o);
        if (lane == 0)
            S[((size_t)b * LN + (LN - LQN) + qp) * LN + (LN - LQN) + kp] += s;
    }
}

// ---------------------------------------------------------------------------
// Kernel 3: in-place row softmax of (S/sqrt(D) + log(1-mask)). Warp per row.
// ---------------------------------------------------------------------------
__global__ __launch_bounds__(256) void softmax_kernel(float* __restrict__ S,
                                                      const float* __restrict__ M)
{
    const int row  = blockIdx.x * 8 + (threadIdx.x >> 5);
    const int lane = threadIdx.x & 31;
    const int b    = row >> 9;

    float* p = S + (size_t)row * LN;
    const float* mp = M + (size_t)b * LN;

    float x[16];
    float mx = -1e30f;
    #pragma unroll
    for (int j = 0; j < 4; j++) {
        int col = lane * 4 + j * 128;
        float4 v  = *(const float4*)(p + col);
        float4 km = *(const float4*)(mp + col);
        float l0 = (km.x != 0.f) ? logf(1.f - km.x) : 0.f;
        float l1 = (km.y != 0.f) ? logf(1.f - km.y) : 0.f;
        float l2 = (km.z != 0.f) ? logf(1.f - km.z) : 0.f;
        float l3 = (km.w != 0.f) ? logf(1.f - km.w) : 0.f;
        x[j * 4 + 0] = v.x * INV_SQRT_D + l0;
        x[j * 4 + 1] = v.y * INV_SQRT_D + l1;
        x[j * 4 + 2] = v.z * INV_SQRT_D + l2;
        x[j * 4 + 3] = v.w * INV_SQRT_D + l3;
        mx = fmaxf(mx, fmaxf(fmaxf(x[j*4], x[j*4+1]), fmaxf(x[j*4+2], x[j*4+3])));
    }
    #pragma unroll
    for (int o = 16; o; o >>= 1) mx = fmaxf(mx, __shfl_xor_sync(0xffffffffu, mx, o));

    float e[16];
    float s = 0.f;
    #pragma unroll
    for (int i = 0; i < 16; i++) { e[i] = __expf(x[i] - mx); s += e[i]; }
    #pragma unroll
    for (int o = 16; o; o >>= 1) s += __shfl_xor_sync(0xffffffffu, s, o);
    float inv = 1.f / s;

    #pragma unroll
    for (int j = 0; j < 4; j++) {
        int col = lane * 4 + j * 128;
        *(float4*)(p + col) = make_float4(e[j*4] * inv, e[j*4+1] * inv,
                                          e[j*4+2] * inv, e[j*4+3] * inv);
    }
}

// ---------------------------------------------------------------------------
// Kernel 4: out[b] = attn[b] @ V[b]    (batched NN sgemm, N = D = 128)
// ---------------------------------------------------------------------------
__global__ __launch_bounds__(256) void pv_kernel(const float* __restrict__ A,
                                                 const float* __restrict__ V,
                                                 float* __restrict__ O)
{
    __shared__ float As[BK][BM + 4];
    __shared__ float Bs[BK][BN];     // direct layout, stride 128 floats

    const int b   = blockIdx.y;
    const int tid = threadIdx.x;
    const float* Ag = A + ((size_t)b * LN + blockIdx.x * BM) * LN;
    const float* Bg = V + (size_t)b * LN * DN;

    const int m0 = (tid >> 4) << 2;
    const int n0 = (tid & 15) << 2;

    unsigned long long acc[8][4];
    #pragma unroll
    for (int i = 0; i < 8; i++)
        #pragma unroll
        for (int j = 0; j < 4; j++) acc[i][j] = 0ull;

    for (int kb = 0; kb < LN; kb += BK) {
        #pragma unroll
        for (int i = 0; i < 2; i++) {
            int idx = tid + i * 256;
            int r = idx >> 2;
            int c = (idx & 3) << 2;
            float4 va = *(const float4*)(Ag + (size_t)r * LN + kb + c);
            As[c + 0][r] = va.x; As[c + 1][r] = va.y;
            As[c + 2][r] = va.z; As[c + 3][r] = va.w;
            int row = idx >> 5;
            int col = (idx & 31) << 2;
            *(float4*)&Bs[row][col] = *(const float4*)(Bg + (size_t)(kb + row) * DN + col);
        }
        __syncthreads();

        #pragma unroll
        for (int k = 0; k < BK; k++) {
            float4 a0 = *(const float4*)&As[k][m0];
            float4 a1 = *(const float4*)&As[k][m0 + 64];
            ulonglong2 b0 = *(const ulonglong2*)&Bs[k][n0];
            ulonglong2 b1 = *(const ulonglong2*)&Bs[k][n0 + 64];
            unsigned long long ap;
#define PV_ROW(i, av) do { PACK2(ap, av);                         \
            FFMA2(acc[i][0], ap, b0.x, acc[i][0]);                \
            FFMA2(acc[i][1], ap, b0.y, acc[i][1]);                \
            FFMA2(acc[i][2], ap, b1.x, acc[i][2]);                \
            FFMA2(acc[i][3], ap, b1.y, acc[i][3]); } while (0)
            PV_ROW(0, a0.x); PV_ROW(1, a0.y); PV_ROW(2, a0.z); PV_ROW(3, a0.w);
            PV_ROW(4, a1.x); PV_ROW(5, a1.y); PV_ROW(6, a1.z); PV_ROW(7, a1.w);
#undef PV_ROW
        }
        __syncthreads();
    }

    float* Cg = O + ((size_t)b * LN + blockIdx.x * BM) * DN;
    #pragma unroll
    for (int mi = 0; mi < 8; mi++) {
        int m = (mi < 4) ? (m0 + mi) : (m0 + 60 + mi);
        float2 f0 = u2f2(acc[mi][0]);
        float2 f1 = u2f2(acc[mi][1]);
        float2 f2 = u2f2(acc[mi][2]);
        float2 f3 = u2f2(acc[mi][3]);
        *(float4*)(Cg + (size_t)m * DN + n0)      = make_float4(f0.x, f0.y, f1.x, f1.y);
        *(float4*)(Cg + (size_t)m * DN + n0 + 64) = make_float4(f2.x, f2.y, f3.x, f3.y);
    }
}

// ---------------------------------------------------------------------------
extern "C" void kernel_launch(void* const* d_in, const int* in_sizes, int n_in,
                              void* d_out, int out_size)
{
    const float* Q  = (const float*)d_in[0];
    const float* K  = (const float*)d_in[1];
    const float* V  = (const float*)d_in[2];
    const float* R  = (const float*)d_in[3];
    const float* M  = (const float*)d_in[4];

    float* out  = (float*)d_out;                       // [128,512,128]
    float* attn = out + (size_t)BHN * LN * DN;         // [128,512,512]

    dim3 gqk(LN / BN, LN / BM, BHN);                   // (4,4,128)
    qk_kernel<<<gqk, 256>>>(Q, K, attn);

    rel_kernel<<<BHN * LQN, 256>>>(Q, R, attn);        // 8192 blocks

    softmax_kernel<<<BHN * LN / 8, 256>>>(attn, M);    // 8192 blocks

    dim3 gpv(LN / BM, BHN);                            // (4,128)
    pv_kernel<<<gpv, 256>>>(attn, V, out);
}

// round 4
// speedup vs baseline: 1.2823x; 1.2823x over previous
#include <cuda_runtime.h>
#include <cuda_bf16.h>
#include <cstdint>

#define BHN 128
#define LN  512
#define DN  128
#define LQN 64
#define INV_SQRT_D 0.08838834764831843f

// smem tile geometry: 128 rows x 128 cols bf16, row stride 136 halves
#define SSTR   136
#define TILE_B (128 * SSTR * 2)       // 34816 bytes
#define OFF_AHI 0
#define OFF_ALO (1 * TILE_B)
#define OFF_BHI (2 * TILE_B)
#define OFF_BLO (3 * TILE_B)
#define SMEM_T  (4 * TILE_B)          // 139264 bytes

__device__ __forceinline__ uint32_t smem_u32(const void* p) {
    uint32_t a;
    asm("{ .reg .u64 t; cvta.to.shared.u64 t, %1; cvt.u32.u64 %0, t; }" : "=r"(a) : "l"(p));
    return a;
}
__device__ __forceinline__ uint32_t pack_bf2(float a, float b) {
    uint32_t r;
    asm("cvt.rn.bf16x2.f32 %0, %1, %2;" : "=r"(r) : "f"(b), "f"(a));   // lo half = a
    return r;
}

#define LDSM_X4(r0, r1, r2, r3, addr)                                           \
    asm volatile("ldmatrix.sync.aligned.m8n8.x4.shared.b16 {%0,%1,%2,%3}, [%4];"\
                 : "=r"(r0), "=r"(r1), "=r"(r2), "=r"(r3) : "r"(addr))
#define LDSM_X4_T(r0, r1, r2, r3, addr)                                         \
    asm volatile("ldmatrix.sync.aligned.m8n8.x4.trans.shared.b16 {%0,%1,%2,%3}, [%4];"\
                 : "=r"(r0), "=r"(r1), "=r"(r2), "=r"(r3) : "r"(addr))
#define MMA_BF16(c, a, b)                                                       \
    asm volatile("mma.sync.aligned.m16n8k16.row.col.f32.bf16.bf16.f32 "         \
                 "{%0,%1,%2,%3}, {%4,%5,%6,%7}, {%8,%9}, {%0,%1,%2,%3};"        \
                 : "+f"((c)[0]), "+f"((c)[1]), "+f"((c)[2]), "+f"((c)[3])       \
                 : "r"((a)[0]), "r"((a)[1]), "r"((a)[2]), "r"((a)[3]),          \
                   "r"((b)[0]), "r"((b)[1]))

// convert float4 (row r, cols 4*c4..) into hi/lo bf16 smem tiles (stride SSTR)
__device__ __forceinline__ void cvt_store(char* smem, int hi, int lo,
                                          int r, int c4, float4 v) {
    uint32_t off = (uint32_t)(r * SSTR + c4 * 4) * 2u;
    float hx = __bfloat162float(__float2bfloat16_rn(v.x));
    float hy = __bfloat162float(__float2bfloat16_rn(v.y));
    float hz = __bfloat162float(__float2bfloat16_rn(v.z));
    float hw = __bfloat162float(__float2bfloat16_rn(v.w));
    *(uint2*)(smem + hi + off) = make_uint2(pack_bf2(v.x, v.y), pack_bf2(v.z, v.w));
    *(uint2*)(smem + lo + off) = make_uint2(pack_bf2(v.x - hx, v.y - hy),
                                            pack_bf2(v.z - hz, v.w - hw));
}

// 3-chain bf16-split MMA over one 128x128x128 block. Accumulates into acc.
// trans_b = 1 -> B tile stored [k][n] (use ldmatrix.trans), else [n][k].
template <int TRANS_B>
__device__ __forceinline__ void mma_block(uint32_t sb, int warp_m, int warp_n,
                                          int lane, float acc[2][8][4]) {
    const int ar  = lane & 15;
    const int acs = (lane >> 4) << 3;
    // no-trans B lane mapping
    const int br  = (lane & 7) | ((lane >> 4) << 3);
    const int bcs = ((lane >> 3) & 1) << 3;
    // trans B lane mapping
    const int tkr = lane & 15;
    const int tnc = (lane >> 4) << 3;

    const uint32_t ab[3] = {sb + OFF_AHI, sb + OFF_AHI, sb + OFF_ALO};
    const uint32_t bb[3] = {sb + OFF_BHI, sb + OFF_BLO, sb + OFF_BHI};

    #pragma unroll
    for (int ch = 0; ch < 3; ch++) {
        const uint32_t abase = ab[ch], bbase = bb[ch];
        #pragma unroll
        for (int k16 = 0; k16 < 8; k16++) {
            const int kh = k16 * 16;
            uint32_t a[2][4];
            #pragma unroll
            for (int mt = 0; mt < 2; mt++)
                LDSM_X4(a[mt][0], a[mt][1], a[mt][2], a[mt][3],
                        abase + (uint32_t)((warp_m + mt * 16 + ar) * SSTR + kh + acs) * 2u);
            uint32_t bf[8][2];
            #pragma unroll
            for (int p = 0; p < 4; p++) {
                uint32_t r0, r1, r2, r3;
                if (TRANS_B) {
                    LDSM_X4_T(r0, r1, r2, r3,
                        bbase + (uint32_t)((kh + tkr) * SSTR + warp_n + p * 16 + tnc) * 2u);
                } else {
                    LDSM_X4(r0, r1, r2, r3,
                        bbase + (uint32_t)((warp_n + p * 16 + br) * SSTR + kh + bcs) * 2u);
                }
                bf[2 * p][0] = r0; bf[2 * p][1] = r1;
                bf[2 * p + 1][0] = r2; bf[2 * p + 1][1] = r3;
            }
            #pragma unroll
            for (int mt = 0; mt < 2; mt++)
                #pragma unroll
                for (int nt = 0; nt < 8; nt++)
                    MMA_BF16(acc[mt][nt], a[mt], bf[nt]);
        }
    }
}

// ---------------------------------------------------------------------------
// Kernel 1: S[b,q,k] = Q·Kᵀ   (tensor cores, bf16 split)
// ---------------------------------------------------------------------------
__global__ __launch_bounds__(256) void qk_tc(const float* __restrict__ Q,
                                             const float* __restrict__ Km,
                                             float* __restrict__ S)
{
    extern __shared__ char smem[];
    const int tid = threadIdx.x, wid = tid >> 5, lane = tid & 31;
    const uint32_t sb = smem_u32(smem);
    const int b = blockIdx.z;

    const float* Ag = Q  + ((size_t)b * LN + blockIdx.y * 128) * DN;
    const float* Bg = Km + ((size_t)b * LN + blockIdx.x * 128) * DN;

    #pragma unroll 4
    for (int i = 0; i < 16; i++) {
        int idx = tid + 256 * i;
        int r = idx >> 5, c4 = idx & 31;
        cvt_store(smem, OFF_AHI, OFF_ALO, r, c4, *(const float4*)(Ag + r * DN + c4 * 4));
        cvt_store(smem, OFF_BHI, OFF_BLO, r, c4, *(const float4*)(Bg + r * DN + c4 * 4));
    }
    __syncthreads();

    const int warp_m = (wid & 3) * 32;
    const int warp_n = (wid >> 2) * 64;
    float acc[2][8][4];
    #pragma unroll
    for (int mt = 0; mt < 2; mt++)
        #pragma unroll
        for (int nt = 0; nt < 8; nt++)
            #pragma unroll
            for (int j = 0; j < 4; j++) acc[mt][nt][j] = 0.f;

    mma_block<0>(sb, warp_m, warp_n, lane, acc);

    float* Cg = S + ((size_t)b * LN + blockIdx.y * 128) * LN + blockIdx.x * 128;
    const int rq = lane >> 2, cq = (lane & 3) * 2;
    #pragma unroll
    for (int mt = 0; mt < 2; mt++)
        #pragma unroll
        for (int nt = 0; nt < 8; nt++) {
            int row = warp_m + mt * 16 + rq;
            int col = warp_n + nt * 8 + cq;
            *(float2*)(Cg + (size_t)row * LN + col)       = make_float2(acc[mt][nt][0], acc[mt][nt][1]);
            *(float2*)(Cg + (size_t)(row + 8) * LN + col) = make_float2(acc[mt][nt][2], acc[mt][nt][3]);
        }
}

// ---------------------------------------------------------------------------
// Kernel 4: out[b] = attn[b] @ V[b]   (tensor cores, bf16 split, V via trans)
// ---------------------------------------------------------------------------
__global__ __launch_bounds__(256) void pv_tc(const float* __restrict__ A,
                                             const float* __restrict__ V,
                                             float* __restrict__ O)
{
    extern __shared__ char smem[];
    const int tid = threadIdx.x, wid = tid >> 5, lane = tid & 31;
    const uint32_t sb = smem_u32(smem);
    const int b = blockIdx.y;

    const float* Ag = A + ((size_t)b * LN + blockIdx.x * 128) * LN;
    const float* Vg = V + (size_t)b * LN * DN;

    const int warp_m = (wid & 3) * 32;
    const int warp_n = (wid >> 2) * 64;
    float acc[2][8][4];
    #pragma unroll
    for (int mt = 0; mt < 2; mt++)
        #pragma unroll
        for (int nt = 0; nt < 8; nt++)
            #pragma unroll
            for (int j = 0; j < 4; j++) acc[mt][nt][j] = 0.f;

    for (int kb = 0; kb < 4; kb++) {
        if (kb) __syncthreads();               // all warps done reading smem
        #pragma unroll 4
        for (int i = 0; i < 16; i++) {
            int idx = tid + 256 * i;
            int r = idx >> 5, c4 = idx & 31;
            cvt_store(smem, OFF_AHI, OFF_ALO, r, c4,
                      *(const float4*)(Ag + (size_t)r * LN + kb * 128 + c4 * 4));
            cvt_store(smem, OFF_BHI, OFF_BLO, r, c4,
                      *(const float4*)(Vg + (size_t)(kb * 128 + r) * DN + c4 * 4));
        }
        __syncthreads();
        mma_block<1>(sb, warp_m, warp_n, lane, acc);
    }

    float* Cg = O + ((size_t)b * LN + blockIdx.x * 128) * DN;
    const int rq = lane >> 2, cq = (lane & 3) * 2;
    #pragma unroll
    for (int mt = 0; mt < 2; mt++)
        #pragma unroll
        for (int nt = 0; nt < 8; nt++) {
            int row = warp_m + mt * 16 + rq;
            int col = warp_n + nt * 8 + cq;
            *(float2*)(Cg + (size_t)row * DN + col)       = make_float2(acc[mt][nt][0], acc[mt][nt][1]);
            *(float2*)(Cg + (size_t)(row + 8) * DN + col) = make_float2(acc[mt][nt][2], acc[mt][nt][3]);
        }
}

// ---------------------------------------------------------------------------
// Kernel 2: S[b, 448+q', 448+k'] += dot(R[b,q',k',:], Q[b,448+q',:])
// ---------------------------------------------------------------------------
__global__ __launch_bounds__(256) void rel_kernel(const float* __restrict__ Q,
                                                  const float* __restrict__ R,
                                                  float* __restrict__ S)
{
    __shared__ float qrow[DN];
    const int b  = blockIdx.x >> 6;
    const int qp = blockIdx.x & 63;
    const int tid = threadIdx.x;

    if (tid < 32)
        ((float4*)qrow)[tid] =
            *(const float4*)(Q + ((size_t)b * LN + (LN - LQN) + qp) * DN + tid * 4);
    __syncthreads();

    const int w = tid >> 5, lane = tid & 31;
    const float4 qv = ((const float4*)qrow)[lane];

    #pragma unroll
    for (int i = 0; i < 8; i++) {
        int kp = w + i * 8;
        const float4* rp = (const float4*)(R + (((size_t)b * LQN + qp) * LQN + kp) * DN);
        float4 rv = rp[lane];
        float s = rv.x * qv.x + rv.y * qv.y + rv.z * qv.z + rv.w * qv.w;
        #pragma unroll
        for (int o = 16; o; o >>= 1) s += __shfl_xor_sync(0xffffffffu, s, o);
        if (lane == 0)
            S[((size_t)b * LN + (LN - LQN) + qp) * LN + (LN - LQN) + kp] += s;
    }
}

// ---------------------------------------------------------------------------
// Kernel 3: in-place row softmax of (S/sqrt(D) + log(1-mask)). Warp per row.
// ---------------------------------------------------------------------------
__global__ __launch_bounds__(256) void softmax_kernel(float* __restrict__ S,
                                                      const float* __restrict__ M)
{
    const int row  = blockIdx.x * 8 + (threadIdx.x >> 5);
    const int lane = threadIdx.x & 31;
    const int b    = row >> 9;

    float* p = S + (size_t)row * LN;
    const float* mp = M + (size_t)b * LN;

    float x[16];
    float mx = -1e30f;
    #pragma unroll
    for (int j = 0; j < 4; j++) {
        int col = lane * 4 + j * 128;
        float4 v  = *(const float4*)(p + col);
        float4 km = *(const float4*)(mp + col);
        float l0 = (km.x != 0.f) ? logf(1.f - km.x) : 0.f;
        float l1 = (km.y != 0.f) ? logf(1.f - km.y) : 0.f;
        float l2 = (km.z != 0.f) ? logf(1.f - km.z) : 0.f;
        float l3 = (km.w != 0.f) ? logf(1.f - km.w) : 0.f;
        x[j * 4 + 0] = v.x * INV_SQRT_D + l0;
        x[j * 4 + 1] = v.y * INV_SQRT_D + l1;
        x[j * 4 + 2] = v.z * INV_SQRT_D + l2;
        x[j * 4 + 3] = v.w * INV_SQRT_D + l3;
        mx = fmaxf(mx, fmaxf(fmaxf(x[j*4], x[j*4+1]), fmaxf(x[j*4+2], x[j*4+3])));
    }
    #pragma unroll
    for (int o = 16; o; o >>= 1) mx = fmaxf(mx, __shfl_xor_sync(0xffffffffu, mx, o));

    float e[16];
    float s = 0.f;
    #pragma unroll
    for (int i = 0; i < 16; i++) { e[i] = __expf(x[i] - mx); s += e[i]; }
    #pragma unroll
    for (int o = 16; o; o >>= 1) s += __shfl_xor_sync(0xffffffffu, s, o);
    float inv = 1.f / s;

    #pragma unroll
    for (int j = 0; j < 4; j++) {
        int col = lane * 4 + j * 128;
        *(float4*)(p + col) = make_float4(e[j*4] * inv, e[j*4+1] * inv,
                                          e[j*4+2] * inv, e[j*4+3] * inv);
    }
}

// ---------------------------------------------------------------------------
extern "C" void kernel_launch(void* const* d_in, const int* in_sizes, int n_in,
                              void* d_out, int out_size)
{
    const float* Q  = (const float*)d_in[0];
    const float* K  = (const float*)d_in[1];
    const float* V  = (const float*)d_in[2];
    const float* R  = (const float*)d_in[3];
    const float* M  = (const float*)d_in[4];

    float* out  = (float*)d_out;                       // [128,512,128]
    float* attn = out + (size_t)BHN * LN * DN;         // [128,512,512]

    static bool attr_set = false;
    if (!attr_set) {
        cudaFuncSetAttribute(qk_tc, cudaFuncAttributeMaxDynamicSharedMemorySize, SMEM_T);
        cudaFuncSetAttribute(pv_tc, cudaFuncAttributeMaxDynamicSharedMemorySize, SMEM_T);
        attr_set = true;
    }

    dim3 gqk(LN / 128, LN / 128, BHN);                 // (4,4,128)
    qk_tc<<<gqk, 256, SMEM_T>>>(Q, K, attn);

    rel_kernel<<<BHN * LQN, 256>>>(Q, R, attn);        // 8192 blocks

    softmax_kernel<<<BHN * LN / 8, 256>>>(attn, M);    // 8192 blocks

    dim3 gpv(LN / 128, BHN);                           // (4,128)
    pv_tc<<<gpv, 256, SMEM_T>>>(attn, V, out);
}

// round 5
// speedup vs baseline: 1.3398x; 1.0448x over previous
#include <cuda_runtime.h>
#include <cuda_bf16.h>
#include <cstdint>

#define BHN 128
#define LN  512
#define DN  128
#define LQN 64
#define INV_SQRT_D 0.08838834764831843f

// smem geometry: row stride 136 halves (bank-conflict-free ldmatrix)
#define SSTR 136
#define OFF_QHI 0
#define OFF_QLO 17408
#define OFF_BHI 34816
#define OFF_BLO 69632
#define OFF_PHI 104448
#define OFF_PLO 121856
#define OFF_MASK 139264
#define OFF_RMAX 141312
#define OFF_RSUM 141824
#define SMEM_T  142336

__device__ float g_Srel[(size_t)BHN * LQN * LQN];   // rel logits scratch (2 MB)

__device__ __forceinline__ uint32_t smem_u32(const void* p) {
    uint32_t a;
    asm("{ .reg .u64 t; cvta.to.shared.u64 t, %1; cvt.u32.u64 %0, t; }" : "=r"(a) : "l"(p));
    return a;
}
__device__ __forceinline__ uint32_t pack_bf2(float a, float b) {
    uint32_t r;
    asm("cvt.rn.bf16x2.f32 %0, %1, %2;" : "=r"(r) : "f"(b), "f"(a));   // lo half = a
    return r;
}

#define LDSM_X4(r0, r1, r2, r3, addr)                                           \
    asm volatile("ldmatrix.sync.aligned.m8n8.x4.shared.b16 {%0,%1,%2,%3}, [%4];"\
                 : "=r"(r0), "=r"(r1), "=r"(r2), "=r"(r3) : "r"(addr))
#define LDSM_X4_T(r0, r1, r2, r3, addr)                                         \
    asm volatile("ldmatrix.sync.aligned.m8n8.x4.trans.shared.b16 {%0,%1,%2,%3}, [%4];"\
                 : "=r"(r0), "=r"(r1), "=r"(r2), "=r"(r3) : "r"(addr))
#define MMA_BF16(c, a, b)                                                       \
    asm volatile("mma.sync.aligned.m16n8k16.row.col.f32.bf16.bf16.f32 "         \
                 "{%0,%1,%2,%3}, {%4,%5,%6,%7}, {%8,%9}, {%0,%1,%2,%3};"        \
                 : "+f"((c)[0]), "+f"((c)[1]), "+f"((c)[2]), "+f"((c)[3])       \
                 : "r"((a)[0]), "r"((a)[1]), "r"((a)[2]), "r"((a)[3]),          \
                   "r"((b)[0]), "r"((b)[1]))

// convert float4 (row r, cols 4*c4..) into hi/lo bf16 smem tiles (stride SSTR)
__device__ __forceinline__ void cvt_store(char* smem, int hi, int lo,
                                          int r, int c4, float4 v) {
    uint32_t off = (uint32_t)(r * SSTR + c4 * 4) * 2u;
    float hx = __bfloat162float(__float2bfloat16_rn(v.x));
    float hy = __bfloat162float(__float2bfloat16_rn(v.y));
    float hz = __bfloat162float(__float2bfloat16_rn(v.z));
    float hw = __bfloat162float(__float2bfloat16_rn(v.w));
    *(uint2*)(smem + hi + off) = make_uint2(pack_bf2(v.x, v.y), pack_bf2(v.z, v.w));
    *(uint2*)(smem + lo + off) = make_uint2(pack_bf2(v.x - hx, v.y - hy),
                                            pack_bf2(v.z - hz, v.w - hw));
}

// QK chunk: A = Q tile (rows warp_m..+16, K-major), B = K chunk (K-major), 3 chains
__device__ __forceinline__ void mma_chunk_qk(uint32_t sb, int warp_m, int warp_n,
                                             int lane, float acc[8][4]) {
    const int ar  = lane & 15, acs = (lane >> 4) << 3;
    const int br  = (lane & 7) | ((lane >> 4) << 3), bcs = ((lane >> 3) & 1) << 3;
    const uint32_t ab[3] = {sb + OFF_QHI, sb + OFF_QHI, sb + OFF_QLO};
    const uint32_t bb[3] = {sb + OFF_BHI, sb + OFF_BLO, sb + OFF_BHI};
    #pragma unroll
    for (int ch = 0; ch < 3; ch++) {
        #pragma unroll
        for (int k16 = 0; k16 < 8; k16++) {
            const int kh = k16 * 16;
            uint32_t a[4];
            LDSM_X4(a[0], a[1], a[2], a[3],
                    ab[ch] + (uint32_t)((warp_m + ar) * SSTR + kh + acs) * 2u);
            uint32_t bf[8][2];
            #pragma unroll
            for (int p = 0; p < 4; p++) {
                uint32_t r0, r1, r2, r3;
                LDSM_X4(r0, r1, r2, r3,
                        bb[ch] + (uint32_t)((warp_n + p * 16 + br) * SSTR + kh + bcs) * 2u);
                bf[2*p][0] = r0; bf[2*p][1] = r1;
                bf[2*p+1][0] = r2; bf[2*p+1][1] = r3;
            }
            #pragma unroll
            for (int nt = 0; nt < 8; nt++) MMA_BF16(acc[nt], a, bf[nt]);
        }
    }
}

// PV chunk: A = P tile (rows warp_m..+16, K-major), B = V chunk ([k][d], trans), 3 chains
__device__ __forceinline__ void mma_chunk_pv(uint32_t sb, int warp_m, int warp_n,
                                             int lane, float acc[8][4]) {
    const int ar  = lane & 15, acs = (lane >> 4) << 3;
    const int tkr = lane & 15, tnc = (lane >> 4) << 3;
    const uint32_t ab[3] = {sb + OFF_PHI, sb + OFF_PHI, sb + OFF_PLO};
    const uint32_t bb[3] = {sb + OFF_BHI, sb + OFF_BLO, sb + OFF_BHI};
    #pragma unroll
    for (int ch = 0; ch < 3; ch++) {
        #pragma unroll
        for (int k16 = 0; k16 < 8; k16++) {
            const int kh = k16 * 16;
            uint32_t a[4];
            LDSM_X4(a[0], a[1], a[2], a[3],
                    ab[ch] + (uint32_t)((warp_m + ar) * SSTR + kh + acs) * 2u);
            uint32_t bf[8][2];
            #pragma unroll
            for (int p = 0; p < 4; p++) {
                uint32_t r0, r1, r2, r3;
                LDSM_X4_T(r0, r1, r2, r3,
                          bb[ch] + (uint32_t)((kh + tkr) * SSTR + warp_n + p * 16 + tnc) * 2u);
                bf[2*p][0] = r0; bf[2*p][1] = r1;
                bf[2*p+1][0] = r2; bf[2*p+1][1] = r3;
            }
            #pragma unroll
            for (int nt = 0; nt < 8; nt++) MMA_BF16(acc[nt], a, bf[nt]);
        }
    }
}

// ---------------------------------------------------------------------------
// Fused: QK^T + rel + scale + mask + softmax + attn-write + PV, per 64-row q tile
// ---------------------------------------------------------------------------
__global__ __launch_bounds__(256, 1) void fused_attn(const float* __restrict__ Q,
                                                     const float* __restrict__ K,
                                                     const float* __restrict__ V,
                                                     const float* __restrict__ Mask,
                                                     float* __restrict__ attn,
                                                     float* __restrict__ out)
{
    extern __shared__ char smem[];
    const int tid = threadIdx.x, wid = tid >> 5, lane = tid & 31;
    const uint32_t sb = smem_u32(smem);
    const int b = blockIdx.y, qt = blockIdx.x;

    // masked-logits row: log(1 - mask[b, :]) into smem
    {
        float* sm = (float*)(smem + OFF_MASK);
        float m0 = Mask[(size_t)b * LN + tid];
        sm[tid] = (m0 != 0.f) ? logf(1.f - m0) : 0.f;
        float m1 = Mask[(size_t)b * LN + 256 + tid];
        sm[256 + tid] = (m1 != 0.f) ? logf(1.f - m1) : 0.f;
    }
    // Q tile: 64 x 128
    {
        const float* Qg = Q + ((size_t)b * LN + qt * 64) * DN;
        #pragma unroll
        for (int i = 0; i < 8; i++) {
            int idx = tid + 256 * i;
            int r = idx >> 5, c4 = idx & 31;
            cvt_store(smem, OFF_QHI, OFF_QLO, r, c4, *(const float4*)(Qg + r * DN + c4 * 4));
        }
    }
    __syncthreads();

    const int warp_m = (wid & 3) * 16;      // q rows within tile
    const int warp_n = (wid >> 2) * 64;     // cols within 128-col chunk

    float accS[4][8][4];
    #pragma unroll
    for (int kb = 0; kb < 4; kb++)
        #pragma unroll
        for (int nt = 0; nt < 8; nt++)
            #pragma unroll
            for (int j = 0; j < 4; j++) accS[kb][nt][j] = 0.f;

    // ---- QK over 4 K chunks ----
    for (int kb = 0; kb < 4; kb++) {
        if (kb) __syncthreads();
        const float* Kg = K + ((size_t)b * LN + kb * 128) * DN;
        #pragma unroll
        for (int i = 0; i < 16; i++) {
            int idx = tid + 256 * i;
            int r = idx >> 5, c4 = idx & 31;
            cvt_store(smem, OFF_BHI, OFF_BLO, r, c4, *(const float4*)(Kg + r * DN + c4 * 4));
        }
        __syncthreads();
        mma_chunk_qk(sb, warp_m, warp_n, lane, accS[kb]);
    }

    // ---- rel add (only q rows 448.., k cols 448..) ----
    const int r0 = warp_m + (lane >> 2), r1 = r0 + 8;
    const int cq = (lane & 3) * 2;
    if (qt == 7 && warp_n == 64) {
        #pragma unroll
        for (int nt = 0; nt < 8; nt++) {
            int kp = nt * 8 + cq;
            float2 s0 = *(const float2*)&g_Srel[((size_t)b * LQN + r0) * LQN + kp];
            float2 s1 = *(const float2*)&g_Srel[((size_t)b * LQN + r1) * LQN + kp];
            accS[3][nt][0] += s0.x; accS[3][nt][1] += s0.y;
            accS[3][nt][2] += s1.x; accS[3][nt][3] += s1.y;
        }
    }

    // ---- scale + mask + row max ----
    const float* sm = (const float*)(smem + OFF_MASK);
    float mx0 = -1e30f, mx1 = -1e30f;
    #pragma unroll
    for (int kb = 0; kb < 4; kb++)
        #pragma unroll
        for (int nt = 0; nt < 8; nt++) {
            int c = kb * 128 + warp_n + nt * 8 + cq;
            float ml0 = sm[c], ml1 = sm[c + 1];
            float* a = accS[kb][nt];
            a[0] = fmaf(a[0], INV_SQRT_D, ml0);
            a[1] = fmaf(a[1], INV_SQRT_D, ml1);
            a[2] = fmaf(a[2], INV_SQRT_D, ml0);
            a[3] = fmaf(a[3], INV_SQRT_D, ml1);
            mx0 = fmaxf(mx0, fmaxf(a[0], a[1]));
            mx1 = fmaxf(mx1, fmaxf(a[2], a[3]));
        }
    mx0 = fmaxf(mx0, __shfl_xor_sync(0xffffffffu, mx0, 1));
    mx0 = fmaxf(mx0, __shfl_xor_sync(0xffffffffu, mx0, 2));
    mx1 = fmaxf(mx1, __shfl_xor_sync(0xffffffffu, mx1, 1));
    mx1 = fmaxf(mx1, __shfl_xor_sync(0xffffffffu, mx1, 2));
    float* rmax = (float*)(smem + OFF_RMAX);
    if ((lane & 3) == 0) { rmax[r0 * 2 + (wid >> 2)] = mx0; rmax[r1 * 2 + (wid >> 2)] = mx1; }
    __syncthreads();
    mx0 = fmaxf(rmax[r0 * 2], rmax[r0 * 2 + 1]);
    mx1 = fmaxf(rmax[r1 * 2], rmax[r1 * 2 + 1]);

    // ---- exp + row sum ----
    float s0 = 0.f, s1 = 0.f;
    #pragma unroll
    for (int kb = 0; kb < 4; kb++)
        #pragma unroll
        for (int nt = 0; nt < 8; nt++) {
            float* a = accS[kb][nt];
            a[0] = __expf(a[0] - mx0); a[1] = __expf(a[1] - mx0);
            a[2] = __expf(a[2] - mx1); a[3] = __expf(a[3] - mx1);
            s0 += a[0] + a[1]; s1 += a[2] + a[3];
        }
    s0 += __shfl_xor_sync(0xffffffffu, s0, 1);
    s0 += __shfl_xor_sync(0xffffffffu, s0, 2);
    s1 += __shfl_xor_sync(0xffffffffu, s1, 1);
    s1 += __shfl_xor_sync(0xffffffffu, s1, 2);
    float* rsum = (float*)(smem + OFF_RSUM);
    if ((lane & 3) == 0) { rsum[r0 * 2 + (wid >> 2)] = s0; rsum[r1 * 2 + (wid >> 2)] = s1; }
    __syncthreads();
    const float inv0 = 1.f / (rsum[r0 * 2] + rsum[r0 * 2 + 1]);
    const float inv1 = 1.f / (rsum[r1 * 2] + rsum[r1 * 2 + 1]);

    // ---- normalize + write attn ----
    float* attnB = attn + ((size_t)b * LN + qt * 64) * LN;
    #pragma unroll
    for (int kb = 0; kb < 4; kb++)
        #pragma unroll
        for (int nt = 0; nt < 8; nt++) {
            int c = kb * 128 + warp_n + nt * 8 + cq;
            float* a = accS[kb][nt];
            a[0] *= inv0; a[1] *= inv0; a[2] *= inv1; a[3] *= inv1;
            *(float2*)(attnB + (size_t)r0 * LN + c) = make_float2(a[0], a[1]);
            *(float2*)(attnB + (size_t)r1 * LN + c) = make_float2(a[2], a[3]);
        }

    // ---- PV over 4 chunks ----
    const int warp_n2 = (wid >> 2) * 64;    // d cols
    float accO[8][4];
    #pragma unroll
    for (int nt = 0; nt < 8; nt++)
        #pragma unroll
        for (int j = 0; j < 4; j++) accO[nt][j] = 0.f;

    for (int kb = 0; kb < 4; kb++) {
        __syncthreads();   // previous chunk's smem fully consumed
        // P chunk regs -> bf16 hi/lo smem (K-major [q][k])
        #pragma unroll
        for (int nt = 0; nt < 8; nt++) {
            int c = warp_n + nt * 8 + cq;
            const float* a = accS[kb][nt];
            float h0 = __bfloat162float(__float2bfloat16_rn(a[0]));
            float h1 = __bfloat162float(__float2bfloat16_rn(a[1]));
            float h2 = __bfloat162float(__float2bfloat16_rn(a[2]));
            float h3 = __bfloat162float(__float2bfloat16_rn(a[3]));
            uint32_t o0 = (uint32_t)(r0 * SSTR + c) * 2u;
            uint32_t o1 = (uint32_t)(r1 * SSTR + c) * 2u;
            *(uint32_t*)(smem + OFF_PHI + o0) = pack_bf2(a[0], a[1]);
            *(uint32_t*)(smem + OFF_PLO + o0) = pack_bf2(a[0] - h0, a[1] - h1);
            *(uint32_t*)(smem + OFF_PHI + o1) = pack_bf2(a[2], a[3]);
            *(uint32_t*)(smem + OFF_PLO + o1) = pack_bf2(a[2] - h2, a[3] - h3);
        }
        // V chunk
        const float* Vg = V + ((size_t)b * LN + kb * 128) * DN;
        #pragma unroll
        for (int i = 0; i < 16; i++) {
            int idx = tid + 256 * i;
            int r = idx >> 5, c4 = idx & 31;
            cvt_store(smem, OFF_BHI, OFF_BLO, r, c4, *(const float4*)(Vg + r * DN + c4 * 4));
        }
        __syncthreads();
        mma_chunk_pv(sb, warp_m, warp_n2, lane, accO);
    }

    // ---- write out ----
    float* Og = out + ((size_t)b * LN + qt * 64) * DN;
    #pragma unroll
    for (int nt = 0; nt < 8; nt++) {
        int c = warp_n2 + nt * 8 + cq;
        *(float2*)(Og + (size_t)r0 * DN + c) = make_float2(accO[nt][0], accO[nt][1]);
        *(float2*)(Og + (size_t)r1 * DN + c) = make_float2(accO[nt][2], accO[nt][3]);
    }
}

// ---------------------------------------------------------------------------
// rel: g_Srel[b,q',k'] = dot(R[b,q',k',:], Q[b,448+q',:])
// ---------------------------------------------------------------------------
__global__ __launch_bounds__(256) void rel_kernel(const float* __restrict__ Q,
                                                  const float* __restrict__ R)
{
    __shared__ float qrow[DN];
    const int b  = blockIdx.x >> 6;
    const int qp = blockIdx.x & 63;
    const int tid = threadIdx.x;

    if (tid < 32)
        ((float4*)qrow)[tid] =
            *(const float4*)(Q + ((size_t)b * LN + (LN - LQN) + qp) * DN + tid * 4);
    __syncthreads();

    const int w = tid >> 5, lane = tid & 31;
    const float4 qv = ((const float4*)qrow)[lane];

    #pragma unroll
    for (int i = 0; i < 8; i++) {
        int kp = w + i * 8;
        const float4* rp = (const float4*)(R + (((size_t)b * LQN + qp) * LQN + kp) * DN);
        float4 rv = rp[lane];
        float s = rv.x * qv.x + rv.y * qv.y + rv.z * qv.z + rv.w * qv.w;
        #pragma unroll
        for (int o = 16; o; o >>= 1) s += __shfl_xor_sync(0xffffffffu, s, o);
        if (lane == 0)
            g_Srel[((size_t)b * LQN + qp) * LQN + kp] = s;
    }
}

// ---------------------------------------------------------------------------
extern "C" void kernel_launch(void* const* d_in, const int* in_sizes, int n_in,
                              void* d_out, int out_size)
{
    const float* Q  = (const float*)d_in[0];
    const float* K  = (const float*)d_in[1];
    const float* V  = (const float*)d_in[2];
    const float* R  = (const float*)d_in[3];
    const float* M  = (const float*)d_in[4];

    float* out  = (float*)d_out;                       // [128,512,128]
    float* attn = out + (size_t)BHN * LN * DN;         // [128,512,512]

    static bool attr_set = false;
    if (!attr_set) {
        cudaFuncSetAttribute(fused_attn, cudaFuncAttributeMaxDynamicSharedMemorySize, SMEM_T);
        attr_set = true;
    }

    rel_kernel<<<BHN * LQN, 256>>>(Q, R);              // 8192 blocks

    dim3 g(8, BHN);                                    // (q-tiles, batch-heads)
    fused_attn<<<g, 256, SMEM_T>>>(Q, K, V, M, attn, out);
}

// round 7
// speedup vs baseline: 1.4647x; 1.0932x over previous
#include <cuda_runtime.h>
#include <cuda_bf16.h>
#include <cstdint>

#define BHN 128
#define LN  512
#define DN  128
#define LQN 64
#define INV_SQRT_D 0.08838834764831843f

// smem geometry: row stride 136 halves (conflict-free ldmatrix)
#define SSTR 136
// byte offsets
#define OFF_QHI  0
#define OFF_QLO  8704
#define OFF_B0HI 17408
#define OFF_B0LO 52224
#define OFF_B1HI 87040
#define OFF_B1LO 121856
#define OFF_PHI  156672
#define OFF_PLO  165376
#define OFF_MASK 174080
#define OFF_RMAX 176128
#define OFF_RSUM 176640
#define SMEM_T   177152

__device__ float g_Srel[(size_t)BHN * LQN * LQN];                 // 2 MB
__device__ __nv_bfloat16 g_Khi[(size_t)BHN * LN * DN];            // 16 MB each
__device__ __nv_bfloat16 g_Klo[(size_t)BHN * LN * DN];
__device__ __nv_bfloat16 g_Vhi[(size_t)BHN * LN * DN];
__device__ __nv_bfloat16 g_Vlo[(size_t)BHN * LN * DN];

__device__ __forceinline__ uint32_t smem_u32(const void* p) {
    uint32_t a;
    asm("{ .reg .u64 t; cvta.to.shared.u64 t, %1; cvt.u32.u64 %0, t; }" : "=r"(a) : "l"(p));
    return a;
}
__device__ __forceinline__ uint32_t pack_bf2(float a, float b) {
    uint32_t r;
    asm("cvt.rn.bf16x2.f32 %0, %1, %2;" : "=r"(r) : "f"(b), "f"(a));   // lo half = a
    return r;
}

#define LDSM_X4(r0, r1, r2, r3, addr)                                           \
    asm volatile("ldmatrix.sync.aligned.m8n8.x4.shared.b16 {%0,%1,%2,%3}, [%4];"\
                 : "=r"(r0), "=r"(r1), "=r"(r2), "=r"(r3) : "r"(addr))
#define LDSM_X4_T(r0, r1, r2, r3, addr)                                         \
    asm volatile("ldmatrix.sync.aligned.m8n8.x4.trans.shared.b16 {%0,%1,%2,%3}, [%4];"\
                 : "=r"(r0), "=r"(r1), "=r"(r2), "=r"(r3) : "r"(addr))
#define MMA_BF16(c, a, b)                                                       \
    asm volatile("mma.sync.aligned.m16n8k16.row.col.f32.bf16.bf16.f32 "         \
                 "{%0,%1,%2,%3}, {%4,%5,%6,%7}, {%8,%9}, {%0,%1,%2,%3};"        \
                 : "+f"((c)[0]), "+f"((c)[1]), "+f"((c)[2]), "+f"((c)[3])       \
                 : "r"((a)[0]), "r"((a)[1]), "r"((a)[2]), "r"((a)[3]),          \
                   "r"((b)[0]), "r"((b)[1]))

#define CP16(dst, src)  asm volatile("cp.async.cg.shared.global [%0], [%1], 16;" :: "r"(dst), "l"(src))
#define CP_COMMIT()     asm volatile("cp.async.commit_group;" ::: "memory")
#define CP_WAIT1()      asm volatile("cp.async.wait_group 1;" ::: "memory")
#define CP_WAIT0()      asm volatile("cp.async.wait_group 0;" ::: "memory")

// convert float4 (row r, cols 4*c4..) into hi/lo bf16 smem tiles (stride SSTR)
__device__ __forceinline__ void cvt_store(char* smem, int hi, int lo,
                                          int r, int c4, float4 v) {
    uint32_t off = (uint32_t)(r * SSTR + c4 * 4) * 2u;
    float hx = __bfloat162float(__float2bfloat16_rn(v.x));
    float hy = __bfloat162float(__float2bfloat16_rn(v.y));
    float hz = __bfloat162float(__float2bfloat16_rn(v.z));
    float hw = __bfloat162float(__float2bfloat16_rn(v.w));
    *(uint2*)(smem + hi + off) = make_uint2(pack_bf2(v.x, v.y), pack_bf2(v.z, v.w));
    *(uint2*)(smem + lo + off) = make_uint2(pack_bf2(v.x - hx, v.y - hy),
                                            pack_bf2(v.z - hz, v.w - hw));
}

// async-load one 128x128 bf16 hi/lo chunk (rows = kv index, cols = d) into a buffer
__device__ __forceinline__ void load_chunk(uint32_t dhi, uint32_t dlo,
                                           const __nv_bfloat16* hi,
                                           const __nv_bfloat16* lo,
                                           size_t base, int tid) {
    #pragma unroll
    for (int i = 0; i < 8; i++) {
        int idx = tid + 256 * i;         // 0..2047
        int r = idx >> 4, c8 = idx & 15;
        uint32_t doff = (uint32_t)(r * (SSTR * 2) + c8 * 16);
        CP16(dhi + doff, hi + base + (size_t)r * DN + c8 * 8);
        CP16(dlo + doff, lo + base + (size_t)r * DN + c8 * 8);
    }
}

// QK chunk MMA: A = Q rows warp_m..+16 (K-major), B = buf rows warp_n..+32 (K-major)
__device__ __forceinline__ void mma_qk(uint32_t sb, uint32_t bhi, uint32_t blo,
                                       int warp_m, int warp_n, int lane, float acc[4][4]) {
    const int ar = lane & 15, acs = (lane >> 4) << 3;
    const int br = (lane & 7) | ((lane >> 4) << 3), bcs = ((lane >> 3) & 1) << 3;
    const uint32_t ab[3] = {sb + OFF_QHI, sb + OFF_QHI, sb + OFF_QLO};
    const uint32_t bb[3] = {bhi, blo, bhi};
    #pragma unroll
    for (int ch = 0; ch < 3; ch++) {
        #pragma unroll
        for (int k16 = 0; k16 < 8; k16++) {
            const int kh = k16 * 16;
            uint32_t a[4];
            LDSM_X4(a[0], a[1], a[2], a[3],
                    ab[ch] + (uint32_t)((warp_m + ar) * SSTR + kh + acs) * 2u);
            uint32_t bf[4][2];
            #pragma unroll
            for (int p = 0; p < 2; p++) {
                uint32_t r0, r1, r2, r3;
                LDSM_X4(r0, r1, r2, r3,
                        bb[ch] + (uint32_t)((warp_n + p * 16 + br) * SSTR + kh + bcs) * 2u);
                bf[2*p][0] = r0; bf[2*p][1] = r1;
                bf[2*p+1][0] = r2; bf[2*p+1][1] = r3;
            }
            #pragma unroll
            for (int nt = 0; nt < 4; nt++) MMA_BF16(acc[nt], a, bf[nt]);
        }
    }
}

// PV chunk MMA: A = P rows warp_m..+16 (K-major), B = buf [k][d] via trans
__device__ __forceinline__ void mma_pv(uint32_t sb, uint32_t bhi, uint32_t blo,
                                       int warp_m, int warp_n, int lane, float acc[4][4]) {
    const int ar = lane & 15, acs = (lane >> 4) << 3;
    const int tkr = lane & 15, tnc = (lane >> 4) << 3;
    const uint32_t ab[3] = {sb + OFF_PHI, sb + OFF_PHI, sb + OFF_PLO};
    const uint32_t bb[3] = {bhi, blo, bhi};
    #pragma unroll
    for (int ch = 0; ch < 3; ch++) {
        #pragma unroll
        for (int k16 = 0; k16 < 8; k16++) {
            const int kh = k16 * 16;
            uint32_t a[4];
            LDSM_X4(a[0], a[1], a[2], a[3],
                    ab[ch] + (uint32_t)((warp_m + ar) * SSTR + kh + acs) * 2u);
            uint32_t bf[4][2];
            #pragma unroll
            for (int p = 0; p < 2; p++) {
                uint32_t r0, r1, r2, r3;
                LDSM_X4_T(r0, r1, r2, r3,
                          bb[ch] + (uint32_t)((kh + tkr) * SSTR + warp_n + p * 16 + tnc) * 2u);
                bf[2*p][0] = r0; bf[2*p][1] = r1;
                bf[2*p+1][0] = r2; bf[2*p+1][1] = r3;
            }
            #pragma unroll
            for (int nt = 0; nt < 4; nt++) MMA_BF16(acc[nt], a, bf[nt]);
        }
    }
}

// ---------------------------------------------------------------------------
// prep: K,V fp32 -> bf16 hi/lo global scratch
// ---------------------------------------------------------------------------
__global__ __launch_bounds__(256) void prep_kernel(const float* __restrict__ K,
                                                   const float* __restrict__ V)
{
    size_t i4 = (size_t)blockIdx.x * 256 + threadIdx.x;       // float4 index
    const float* src = blockIdx.y ? V : K;
    __nv_bfloat16* hi = blockIdx.y ? g_Vhi : g_Khi;
    __nv_bfloat16* lo = blockIdx.y ? g_Vlo : g_Klo;
    float4 v = ((const float4*)src)[i4];
    float hx = __bfloat162float(__float2bfloat16_rn(v.x));
    float hy = __bfloat162float(__float2bfloat16_rn(v.y));
    float hz = __bfloat162float(__float2bfloat16_rn(v.z));
    float hw = __bfloat162float(__float2bfloat16_rn(v.w));
    ((uint2*)hi)[i4] = make_uint2(pack_bf2(v.x, v.y), pack_bf2(v.z, v.w));
    ((uint2*)lo)[i4] = make_uint2(pack_bf2(v.x - hx, v.y - hy), pack_bf2(v.z - hz, v.w - hw));
}

// ---------------------------------------------------------------------------
// rel: g_Srel[b,q',k'] = dot(R[b,q',k',:], Q[b,448+q',:])
// ---------------------------------------------------------------------------
__global__ __launch_bounds__(256) void rel_kernel(const float* __restrict__ Q,
                                                  const float* __restrict__ R)
{
    __shared__ float qrow[DN];
    const int b  = blockIdx.x >> 6;
    const int qp = blockIdx.x & 63;
    const int tid = threadIdx.x;

    if (tid < 32)
        ((float4*)qrow)[tid] =
            *(const float4*)(Q + ((size_t)b * LN + (LN - LQN) + qp) * DN + tid * 4);
    __syncthreads();

    const int w = tid >> 5, lane = tid & 31;
    const float4 qv = ((const float4*)qrow)[lane];

    #pragma unroll
    for (int i = 0; i < 8; i++) {
        int kp = w + i * 8;
        const float4* rp = (const float4*)(R + (((size_t)b * LQN + qp) * LQN + kp) * DN);
        float4 rv = rp[lane];
        float s = rv.x * qv.x + rv.y * qv.y + rv.z * qv.z + rv.w * qv.w;
        #pragma unroll
        for (int o = 16; o; o >>= 1) s += __shfl_xor_sync(0xffffffffu, s, o);
        if (lane == 0)
            g_Srel[((size_t)b * LQN + qp) * LQN + kp] = s;
    }
}

// ---------------------------------------------------------------------------
// fused: per 32-row q-tile: QK + rel + softmax + attn write + PV, pipelined
// ---------------------------------------------------------------------------
__global__ __launch_bounds__(256, 1) void fused_attn(const float* __restrict__ Q,
                                                     const float* __restrict__ Mask,
                                                     float* __restrict__ attn,
                                                     float* __restrict__ out)
{
    extern __shared__ char smem[];
    const int tid = threadIdx.x, wid = tid >> 5, lane = tid & 31;
    const uint32_t sb = smem_u32(smem);
    const int b = blockIdx.y, qt = blockIdx.x;
    const size_t bkv = (size_t)b * LN * DN;

    const uint32_t bufhi[2] = {sb + OFF_B0HI, sb + OFF_B1HI};
    const uint32_t buflo[2] = {sb + OFF_B0LO, sb + OFF_B1LO};

    // pipeline prologue: K chunks 0,1
    load_chunk(bufhi[0], buflo[0], g_Khi, g_Klo, bkv + 0 * 128 * DN, tid);
    CP_COMMIT();
    load_chunk(bufhi[1], buflo[1], g_Khi, g_Klo, bkv + 1 * 128 * DN, tid);
    CP_COMMIT();

    // mask logits
    {
        float* sm = (float*)(smem + OFF_MASK);
        float m0 = Mask[(size_t)b * LN + tid];
        sm[tid] = (m0 != 0.f) ? logf(1.f - m0) : 0.f;
        float m1 = Mask[(size_t)b * LN + 256 + tid];
        sm[256 + tid] = (m1 != 0.f) ? logf(1.f - m1) : 0.f;
    }
    // Q tile 32 x 128
    {
        const float* Qg = Q + ((size_t)b * LN + qt * 32) * DN;
        #pragma unroll
        for (int i = 0; i < 4; i++) {
            int idx = tid + 256 * i;
            int r = idx >> 5, c4 = idx & 31;
            cvt_store(smem, OFF_QHI, OFF_QLO, r, c4, *(const float4*)(Qg + r * DN + c4 * 4));
        }
    }

    const int warp_m = (wid & 1) * 16;
    const int warp_n = (wid >> 1) * 32;
    const int r0 = warp_m + (lane >> 2), r1 = r0 + 8;
    const int cq = (lane & 3) * 2;

    float accS[4][4][4];
    #pragma unroll
    for (int kb = 0; kb < 4; kb++)
        #pragma unroll
        for (int nt = 0; nt < 4; nt++)
            #pragma unroll
            for (int j = 0; j < 4; j++) accS[kb][nt][j] = 0.f;

    // ---- QK over 4 chunks (stages 0..3); prefetch stages 2..5 ----
    #pragma unroll
    for (int s = 0; s < 4; s++) {
        CP_WAIT1();
        __syncthreads();
        mma_qk(sb, bufhi[s & 1], buflo[s & 1], warp_m, warp_n, lane, accS[s]);
        __syncthreads();
        // issue stage s+2 into buffer (s)&1
        if (s + 2 < 4)
            load_chunk(bufhi[s & 1], buflo[s & 1], g_Khi, g_Klo,
                       bkv + (size_t)(s + 2) * 128 * DN, tid);
        else
            load_chunk(bufhi[s & 1], buflo[s & 1], g_Vhi, g_Vlo,
                       bkv + (size_t)(s - 2) * 128 * DN, tid);
        CP_COMMIT();
    }

    // ---- rel add: q rows >=448 (qt>=14), k cols >=448 (chunk 3, warp_n>=64) ----
    if (qt >= 14 && warp_n >= 64) {
        const int qp0 = (qt - 14) * 32 + r0;
        #pragma unroll
        for (int nt = 0; nt < 4; nt++) {
            int kp = warp_n - 64 + nt * 8 + cq;
            float2 s0 = *(const float2*)&g_Srel[((size_t)b * LQN + qp0) * LQN + kp];
            float2 s1 = *(const float2*)&g_Srel[((size_t)b * LQN + qp0 + 8) * LQN + kp];
            accS[3][nt][0] += s0.x; accS[3][nt][1] += s0.y;
            accS[3][nt][2] += s1.x; accS[3][nt][3] += s1.y;
        }
    }

    // ---- scale + mask + row max ----
    const float* sm = (const float*)(smem + OFF_MASK);
    float mx0 = -1e30f, mx1 = -1e30f;
    #pragma unroll
    for (int kb = 0; kb < 4; kb++)
        #pragma unroll
        for (int nt = 0; nt < 4; nt++) {
            int c = kb * 128 + warp_n + nt * 8 + cq;
            float ml0 = sm[c], ml1 = sm[c + 1];
            float* a = accS[kb][nt];
            a[0] = fmaf(a[0], INV_SQRT_D, ml0);
            a[1] = fmaf(a[1], INV_SQRT_D, ml1);
            a[2] = fmaf(a[2], INV_SQRT_D, ml0);
            a[3] = fmaf(a[3], INV_SQRT_D, ml1);
            mx0 = fmaxf(mx0, fmaxf(a[0], a[1]));
            mx1 = fmaxf(mx1, fmaxf(a[2], a[3]));
        }
    mx0 = fmaxf(mx0, __shfl_xor_sync(0xffffffffu, mx0, 1));
    mx0 = fmaxf(mx0, __shfl_xor_sync(0xffffffffu, mx0, 2));
    mx1 = fmaxf(mx1, __shfl_xor_sync(0xffffffffu, mx1, 1));
    mx1 = fmaxf(mx1, __shfl_xor_sync(0xffffffffu, mx1, 2));
    float* rmax = (float*)(smem + OFF_RMAX);
    const int nw = wid >> 1;
    if ((lane & 3) == 0) { rmax[r0 * 4 + nw] = mx0; rmax[r1 * 4 + nw] = mx1; }
    __syncthreads();
    mx0 = fmaxf(fmaxf(rmax[r0 * 4], rmax[r0 * 4 + 1]), fmaxf(rmax[r0 * 4 + 2], rmax[r0 * 4 + 3]));
    mx1 = fmaxf(fmaxf(rmax[r1 * 4], rmax[r1 * 4 + 1]), fmaxf(rmax[r1 * 4 + 2], rmax[r1 * 4 + 3]));

    // ---- exp + row sum ----
    float s0 = 0.f, s1 = 0.f;
    #pragma unroll
    for (int kb = 0; kb < 4; kb++)
        #pragma unroll
        for (int nt = 0; nt < 4; nt++) {
            float* a = accS[kb][nt];
            a[0] = __expf(a[0] - mx0); a[1] = __expf(a[1] - mx0);
            a[2] = __expf(a[2] - mx1); a[3] = __expf(a[3] - mx1);
            s0 += a[0] + a[1]; s1 += a[2] + a[3];
        }
    s0 += __shfl_xor_sync(0xffffffffu, s0, 1);
    s0 += __shfl_xor_sync(0xffffffffu, s0, 2);
    s1 += __shfl_xor_sync(0xffffffffu, s1, 1);
    s1 += __shfl_xor_sync(0xffffffffu, s1, 2);
    float* rsum = (float*)(smem + OFF_RSUM);
    if ((lane & 3) == 0) { rsum[r0 * 4 + nw] = s0; rsum[r1 * 4 + nw] = s1; }
    __syncthreads();
    const float inv0 = 1.f / (rsum[r0 * 4] + rsum[r0 * 4 + 1] + rsum[r0 * 4 + 2] + rsum[r0 * 4 + 3]);
    const float inv1 = 1.f / (rsum[r1 * 4] + rsum[r1 * 4 + 1] + rsum[r1 * 4 + 2] + rsum[r1 * 4 + 3]);

    // ---- normalize + write attn ----
    float* attnB = attn + ((size_t)b * LN + qt * 32) * LN;
    #pragma unroll
    for (int kb = 0; kb < 4; kb++)
        #pragma unroll
        for (int nt = 0; nt < 4; nt++) {
            int c = kb * 128 + warp_n + nt * 8 + cq;
            float* a = accS[kb][nt];
            a[0] *= inv0; a[1] *= inv0; a[2] *= inv1; a[3] *= inv1;
            *(float2*)(attnB + (size_t)r0 * LN + c) = make_float2(a[0], a[1]);
            *(float2*)(attnB + (size_t)r1 * LN + c) = make_float2(a[2], a[3]);
        }

    // ---- PV over 4 chunks (stages 4..7); V chunks 2,3 still prefetch ----
    float accO[4][4];
    #pragma unroll
    for (int nt = 0; nt < 4; nt++)
        #pragma unroll
        for (int j = 0; j < 4; j++) accO[nt][j] = 0.f;

    #pragma unroll
    for (int s = 0; s < 4; s++) {
        if (s < 3) { CP_WAIT1(); } else { CP_WAIT0(); }
        __syncthreads();
        // P chunk s -> bf16 hi/lo smem
        #pragma unroll
        for (int nt = 0; nt < 4; nt++) {
            int c = warp_n + nt * 8 + cq;
            const float* a = accS[s][nt];
            float h0 = __bfloat162float(__float2bfloat16_rn(a[0]));
            float h1 = __bfloat162float(__float2bfloat16_rn(a[1]));
            float h2 = __bfloat162float(__float2bfloat16_rn(a[2]));
            float h3 = __bfloat162float(__float2bfloat16_rn(a[3]));
            uint32_t o0 = (uint32_t)(r0 * SSTR + c) * 2u;
            uint32_t o1 = (uint32_t)(r1 * SSTR + c) * 2u;
            *(uint32_t*)(smem + OFF_PHI + o0) = pack_bf2(a[0], a[1]);
            *(uint32_t*)(smem + OFF_PLO + o0) = pack_bf2(a[0] - h0, a[1] - h1);
            *(uint32_t*)(smem + OFF_PHI + o1) = pack_bf2(a[2], a[3]);
            *(uint32_t*)(smem + OFF_PLO + o1) = pack_bf2(a[2] - h2, a[3] - h3);
        }
        __syncthreads();
        mma_pv(sb, bufhi[s & 1], buflo[s & 1], warp_m, warp_n, lane, accO);
        __syncthreads();
        if (s < 2) {
            load_chunk(bufhi[s & 1], buflo[s & 1], g_Vhi, g_Vlo,
                       bkv + (size_t)(s + 2) * 128 * DN, tid);
            CP_COMMIT();
        }
    }

    // ---- write out ----
    float* Og = out + ((size_t)b * LN + qt * 32) * DN;
    #pragma unroll
    for (int nt = 0; nt < 4; nt++) {
        int c = warp_n + nt * 8 + cq;
        *(float2*)(Og + (size_t)r0 * DN + c) = make_float2(accO[nt][0], accO[nt][1]);
        *(float2*)(Og + (size_t)r1 * DN + c) = make_float2(accO[nt][2], accO[nt][3]);
    }
}

// ---------------------------------------------------------------------------
extern "C" void kernel_launch(void* const* d_in, const int* in_sizes, int n_in,
                              void* d_out, int out_size)
{
    const float* Q  = (const float*)d_in[0];
    const float* K  = (const float*)d_in[1];
    const float* V  = (const float*)d_in[2];
    const float* R  = (const float*)d_in[3];
    const float* M  = (const float*)d_in[4];

    float* out  = (float*)d_out;                       // [128,512,128]
    float* attn = out + (size_t)BHN * LN * DN;         // [128,512,512]

    static bool attr_set = false;
    if (!attr_set) {
        cudaFuncSetAttribute(fused_attn, cudaFuncAttributeMaxDynamicSharedMemorySize, SMEM_T);
        attr_set = true;
    }

    dim3 gprep((BHN * LN * DN) / 4 / 256, 2);          // (8192, 2)
    prep_kernel<<<gprep, 256>>>(K, V);

    rel_kernel<<<BHN * LQN, 256>>>(Q, R);              // 8192 blocks

    dim3 g(16, BHN);                                   // (q-tiles, batch-heads)
    fused_attn<<<g, 256, SMEM_T>>>(Q, M, attn, out);
}

// round 8
// speedup vs baseline: 1.5281x; 1.0433x over previous
#include <cuda_runtime.h>
#include <cuda_bf16.h>
#include <cstdint>

#define BHN 128
#define LN  512
#define DN  128
#define LQN 64
#define INV_SQRT_D 0.08838834764831843f

#define SSTR 136
#define OFF_QHI  0
#define OFF_QLO  8704
#define OFF_BHI  17408
#define OFF_BLO  52224
#define OFF_PHI  87040
#define OFF_PLO  95744
#define OFF_MASK 104448
#define OFF_RMAX 106496
#define OFF_RSUM 107008
#define SMEM_T   107520

__device__ float g_Srel[(size_t)BHN * LQN * LQN];                 // 2 MB
__device__ __nv_bfloat16 g_Khi[(size_t)BHN * LN * DN];            // 16 MB each
__device__ __nv_bfloat16 g_Klo[(size_t)BHN * LN * DN];
__device__ __nv_bfloat16 g_Vhi[(size_t)BHN * LN * DN];
__device__ __nv_bfloat16 g_Vlo[(size_t)BHN * LN * DN];

__device__ __forceinline__ uint32_t smem_u32(const void* p) {
    uint32_t a;
    asm("{ .reg .u64 t; cvta.to.shared.u64 t, %1; cvt.u32.u64 %0, t; }" : "=r"(a) : "l"(p));
    return a;
}
__device__ __forceinline__ uint32_t pack_bf2(float a, float b) {
    uint32_t r;
    asm("cvt.rn.bf16x2.f32 %0, %1, %2;" : "=r"(r) : "f"(b), "f"(a));   // lo half = a
    return r;
}

#define LDSM_X4(r0, r1, r2, r3, addr)                                           \
    asm volatile("ldmatrix.sync.aligned.m8n8.x4.shared.b16 {%0,%1,%2,%3}, [%4];"\
                 : "=r"(r0), "=r"(r1), "=r"(r2), "=r"(r3) : "r"(addr))
#define LDSM_X4_T(r0, r1, r2, r3, addr)                                         \
    asm volatile("ldmatrix.sync.aligned.m8n8.x4.trans.shared.b16 {%0,%1,%2,%3}, [%4];"\
                 : "=r"(r0), "=r"(r1), "=r"(r2), "=r"(r3) : "r"(addr))
#define MMA_BF16(c, a, b)                                                       \
    asm volatile("mma.sync.aligned.m16n8k16.row.col.f32.bf16.bf16.f32 "         \
                 "{%0,%1,%2,%3}, {%4,%5,%6,%7}, {%8,%9}, {%0,%1,%2,%3};"        \
                 : "+f"((c)[0]), "+f"((c)[1]), "+f"((c)[2]), "+f"((c)[3])       \
                 : "r"((a)[0]), "r"((a)[1]), "r"((a)[2]), "r"((a)[3]),          \
                   "r"((b)[0]), "r"((b)[1]))

#define CP16(dst, src)  asm volatile("cp.async.cg.shared.global [%0], [%1], 16;" :: "r"(dst), "l"(src))
#define CP_COMMIT()     asm volatile("cp.async.commit_group;" ::: "memory")
#define CP_WAIT0()      asm volatile("cp.async.wait_group 0;" ::: "memory")

// convert float4 (row r, cols 4*c4..) into hi/lo bf16 smem tiles (stride SSTR)
__device__ __forceinline__ void cvt_store(char* smem, int hi, int lo,
                                          int r, int c4, float4 v) {
    uint32_t off = (uint32_t)(r * SSTR + c4 * 4) * 2u;
    float hx = __bfloat162float(__float2bfloat16_rn(v.x));
    float hy = __bfloat162float(__float2bfloat16_rn(v.y));
    float hz = __bfloat162float(__float2bfloat16_rn(v.z));
    float hw = __bfloat162float(__float2bfloat16_rn(v.w));
    *(uint2*)(smem + hi + off) = make_uint2(pack_bf2(v.x, v.y), pack_bf2(v.z, v.w));
    *(uint2*)(smem + lo + off) = make_uint2(pack_bf2(v.x - hx, v.y - hy),
                                            pack_bf2(v.z - hz, v.w - hw));
}

// async-load one 128x128 bf16 hi/lo chunk into the single B buffer (128 threads)
__device__ __forceinline__ void load_chunk(uint32_t sb,
                                           const __nv_bfloat16* hi,
                                           const __nv_bfloat16* lo,
                                           size_t base, int tid) {
    #pragma unroll
    for (int i = 0; i < 16; i++) {
        int idx = tid + 128 * i;         // 0..2047
        int r = idx >> 4, c8 = idx & 15;
        uint32_t doff = (uint32_t)(r * (SSTR * 2) + c8 * 16);
        CP16(sb + OFF_BHI + doff, hi + base + (size_t)r * DN + c8 * 8);
        CP16(sb + OFF_BLO + doff, lo + base + (size_t)r * DN + c8 * 8);
    }
}

// QK chunk MMA: A = Q rows 0..31 (K-major), B = buf rows warp_n..+32 (K-major), m32 x n32
__device__ __forceinline__ void mma_qk(uint32_t sb, int warp_n, int lane,
                                       float acc[2][4][4]) {
    const int ar = lane & 15, acs = (lane >> 4) << 3;
    const int br = (lane & 7) | ((lane >> 4) << 3), bcs = ((lane >> 3) & 1) << 3;
    const uint32_t ab[3] = {sb + OFF_QHI, sb + OFF_QHI, sb + OFF_QLO};
    const uint32_t bb[3] = {sb + OFF_BHI, sb + OFF_BLO, sb + OFF_BHI};
    #pragma unroll
    for (int ch = 0; ch < 3; ch++) {
        #pragma unroll
        for (int k16 = 0; k16 < 8; k16++) {
            const int kh = k16 * 16;
            uint32_t a[2][4];
            #pragma unroll
            for (int mt = 0; mt < 2; mt++)
                LDSM_X4(a[mt][0], a[mt][1], a[mt][2], a[mt][3],
                        ab[ch] + (uint32_t)((mt * 16 + ar) * SSTR + kh + acs) * 2u);
            uint32_t bf[4][2];
            #pragma unroll
            for (int p = 0; p < 2; p++) {
                uint32_t r0, r1, r2, r3;
                LDSM_X4(r0, r1, r2, r3,
                        bb[ch] + (uint32_t)((warp_n + p * 16 + br) * SSTR + kh + bcs) * 2u);
                bf[2*p][0] = r0; bf[2*p][1] = r1;
                bf[2*p+1][0] = r2; bf[2*p+1][1] = r3;
            }
            #pragma unroll
            for (int mt = 0; mt < 2; mt++)
                #pragma unroll
                for (int nt = 0; nt < 4; nt++) MMA_BF16(acc[mt][nt], a[mt], bf[nt]);
        }
    }
}

// PV chunk MMA: A = P rows 0..31 (K-major), B = buf [k][d] via trans, m32 x n32
__device__ __forceinline__ void mma_pv(uint32_t sb, int warp_n, int lane,
                                       float acc[2][4][4]) {
    const int ar = lane & 15, acs = (lane >> 4) << 3;
    const int tkr = lane & 15, tnc = (lane >> 4) << 3;
    const uint32_t ab[3] = {sb + OFF_PHI, sb + OFF_PHI, sb + OFF_PLO};
    const uint32_t bb[3] = {sb + OFF_BHI, sb + OFF_BLO, sb + OFF_BHI};
    #pragma unroll
    for (int ch = 0; ch < 3; ch++) {
        #pragma unroll
        for (int k16 = 0; k16 < 8; k16++) {
            const int kh = k16 * 16;
            uint32_t a[2][4];
            #pragma unroll
            for (int mt = 0; mt < 2; mt++)
                LDSM_X4(a[mt][0], a[mt][1], a[mt][2], a[mt][3],
                        ab[ch] + (uint32_t)((mt * 16 + ar) * SSTR + kh + acs) * 2u);
            uint32_t bf[4][2];
            #pragma unroll
            for (int p = 0; p < 2; p++) {
                uint32_t r0, r1, r2, r3;
                LDSM_X4_T(r0, r1, r2, r3,
                          bb[ch] + (uint32_t)((kh + tkr) * SSTR + warp_n + p * 16 + tnc) * 2u);
                bf[2*p][0] = r0; bf[2*p][1] = r1;
                bf[2*p+1][0] = r2; bf[2*p+1][1] = r3;
            }
            #pragma unroll
            for (int mt = 0; mt < 2; mt++)
                #pragma unroll
                for (int nt = 0; nt < 4; nt++) MMA_BF16(acc[mt][nt], a[mt], bf[nt]);
        }
    }
}

// ---------------------------------------------------------------------------
// prep: K,V fp32 -> bf16 hi/lo global scratch
// ---------------------------------------------------------------------------
__global__ __launch_bounds__(256) void prep_kernel(const float* __restrict__ K,
                                                   const float* __restrict__ V)
{
    size_t i4 = (size_t)blockIdx.x * 256 + threadIdx.x;
    const float* src = blockIdx.y ? V : K;
    __nv_bfloat16* hi = blockIdx.y ? g_Vhi : g_Khi;
    __nv_bfloat16* lo = blockIdx.y ? g_Vlo : g_Klo;
    float4 v = ((const float4*)src)[i4];
    float hx = __bfloat162float(__float2bfloat16_rn(v.x));
    float hy = __bfloat162float(__float2bfloat16_rn(v.y));
    float hz = __bfloat162float(__float2bfloat16_rn(v.z));
    float hw = __bfloat162float(__float2bfloat16_rn(v.w));
    ((uint2*)hi)[i4] = make_uint2(pack_bf2(v.x, v.y), pack_bf2(v.z, v.w));
    ((uint2*)lo)[i4] = make_uint2(pack_bf2(v.x - hx, v.y - hy), pack_bf2(v.z - hz, v.w - hw));
}

// ---------------------------------------------------------------------------
// rel: g_Srel[b,q',k'] = dot(R[b,q',k',:], Q[b,448+q',:])
// ---------------------------------------------------------------------------
__global__ __launch_bounds__(256) void rel_kernel(const float* __restrict__ Q,
                                                  const float* __restrict__ R)
{
    __shared__ float qrow[DN];
    const int b  = blockIdx.x >> 6;
    const int qp = blockIdx.x & 63;
    const int tid = threadIdx.x;

    if (tid < 32)
        ((float4*)qrow)[tid] =
            *(const float4*)(Q + ((size_t)b * LN + (LN - LQN) + qp) * DN + tid * 4);
    __syncthreads();

    const int w = tid >> 5, lane = tid & 31;
    const float4 qv = ((const float4*)qrow)[lane];

    #pragma unroll
    for (int i = 0; i < 8; i++) {
        int kp = w + i * 8;
        const float4* rp = (const float4*)(R + (((size_t)b * LQN + qp) * LQN + kp) * DN);
        float4 rv = rp[lane];
        float s = rv.x * qv.x + rv.y * qv.y + rv.z * qv.z + rv.w * qv.w;
        #pragma unroll
        for (int o = 16; o; o >>= 1) s += __shfl_xor_sync(0xffffffffu, s, o);
        if (lane == 0)
            g_Srel[((size_t)b * LQN + qp) * LQN + kp] = s;
    }
}

// ---------------------------------------------------------------------------
// fused: 128 threads, 4 warps, q-tile 32, warp tile m32 x n32, 2 CTAs/SM
// ---------------------------------------------------------------------------
__global__ __launch_bounds__(128, 2) void fused_attn(const float* __restrict__ Q,
                                                     const float* __restrict__ Mask,
                                                     float* __restrict__ attn,
                                                     float* __restrict__ out)
{
    extern __shared__ char smem[];
    const int tid = threadIdx.x, wid = tid >> 5, lane = tid & 31;
    const uint32_t sb = smem_u32(smem);
    const int b = blockIdx.y, qt = blockIdx.x;
    const size_t bkv = (size_t)b * LN * DN;

    // prologue: K chunk 0 in flight while we convert mask + Q
    load_chunk(sb, g_Khi, g_Klo, bkv, tid);
    CP_COMMIT();

    {
        float* sm = (float*)(smem + OFF_MASK);
        #pragma unroll
        for (int i = 0; i < 4; i++) {
            int idx = tid + 128 * i;
            float m = Mask[(size_t)b * LN + idx];
            sm[idx] = (m != 0.f) ? logf(1.f - m) : 0.f;
        }
    }
    {
        const float* Qg = Q + ((size_t)b * LN + qt * 32) * DN;
        #pragma unroll
        for (int i = 0; i < 8; i++) {
            int idx = tid + 128 * i;
            int r = idx >> 5, c4 = idx & 31;
            cvt_store(smem, OFF_QHI, OFF_QLO, r, c4, *(const float4*)(Qg + r * DN + c4 * 4));
        }
    }

    const int warp_n = wid * 32;
    const int rq = lane >> 2, cq = (lane & 3) * 2;

    float accS[4][2][4][4];
    #pragma unroll
    for (int kb = 0; kb < 4; kb++)
        #pragma unroll
        for (int mt = 0; mt < 2; mt++)
            #pragma unroll
            for (int nt = 0; nt < 4; nt++)
                #pragma unroll
                for (int j = 0; j < 4; j++) accS[kb][mt][nt][j] = 0.f;

    // ---- QK over 4 chunks; at s=3 start V chunk 0 (covers softmax latency) ----
    #pragma unroll
    for (int s = 0; s < 4; s++) {
        CP_WAIT0();
        __syncthreads();
        mma_qk(sb, warp_n, lane, accS[s]);
        __syncthreads();
        if (s < 3) load_chunk(sb, g_Khi, g_Klo, bkv + (size_t)(s + 1) * 128 * DN, tid);
        else       load_chunk(sb, g_Vhi, g_Vlo, bkv, tid);
        CP_COMMIT();
    }

    // ---- rel add: rows 448.. (qt>=14), cols 448.. (chunk 3, warps 2,3) ----
    if (qt >= 14 && wid >= 2) {
        const int qp0 = (qt - 14) * 32;
        #pragma unroll
        for (int mt = 0; mt < 2; mt++) {
            const int row0 = qp0 + mt * 16 + rq;
            #pragma unroll
            for (int nt = 0; nt < 4; nt++) {
                int kp = (wid - 2) * 32 + nt * 8 + cq;
                float2 s0 = *(const float2*)&g_Srel[((size_t)b * LQN + row0) * LQN + kp];
                float2 s1 = *(const float2*)&g_Srel[((size_t)b * LQN + row0 + 8) * LQN + kp];
                accS[3][mt][nt][0] += s0.x; accS[3][mt][nt][1] += s0.y;
                accS[3][mt][nt][2] += s1.x; accS[3][mt][nt][3] += s1.y;
            }
        }
    }

    // ---- scale + mask + row max ----
    const float* sm = (const float*)(smem + OFF_MASK);
    float mx[2][2];
    mx[0][0] = mx[0][1] = mx[1][0] = mx[1][1] = -1e30f;
    #pragma unroll
    for (int kb = 0; kb < 4; kb++)
        #pragma unroll
        for (int mt = 0; mt < 2; mt++)
            #pragma unroll
            for (int nt = 0; nt < 4; nt++) {
                int c = kb * 128 + warp_n + nt * 8 + cq;
                float ml0 = sm[c], ml1 = sm[c + 1];
                float* a = accS[kb][mt][nt];
                a[0] = fmaf(a[0], INV_SQRT_D, ml0);
                a[1] = fmaf(a[1], INV_SQRT_D, ml1);
                a[2] = fmaf(a[2], INV_SQRT_D, ml0);
                a[3] = fmaf(a[3], INV_SQRT_D, ml1);
                mx[mt][0] = fmaxf(mx[mt][0], fmaxf(a[0], a[1]));
                mx[mt][1] = fmaxf(mx[mt][1], fmaxf(a[2], a[3]));
            }
    #pragma unroll
    for (int mt = 0; mt < 2; mt++)
        #pragma unroll
        for (int h = 0; h < 2; h++) {
            mx[mt][h] = fmaxf(mx[mt][h], __shfl_xor_sync(0xffffffffu, mx[mt][h], 1));
            mx[mt][h] = fmaxf(mx[mt][h], __shfl_xor_sync(0xffffffffu, mx[mt][h], 2));
        }
    float* rmax = (float*)(smem + OFF_RMAX);
    if ((lane & 3) == 0)
        #pragma unroll
        for (int mt = 0; mt < 2; mt++)
            #pragma unroll
            for (int h = 0; h < 2; h++)
                rmax[(mt * 16 + h * 8 + rq) * 4 + wid] = mx[mt][h];
    __syncthreads();
    #pragma unroll
    for (int mt = 0; mt < 2; mt++)
        #pragma unroll
        for (int h = 0; h < 2; h++) {
            const float* r4 = &rmax[(mt * 16 + h * 8 + rq) * 4];
            mx[mt][h] = fmaxf(fmaxf(r4[0], r4[1]), fmaxf(r4[2], r4[3]));
        }

    // ---- exp + row sum ----
    float sum[2][2] = {{0.f, 0.f}, {0.f, 0.f}};
    #pragma unroll
    for (int kb = 0; kb < 4; kb++)
        #pragma unroll
        for (int mt = 0; mt < 2; mt++)
            #pragma unroll
            for (int nt = 0; nt < 4; nt++) {
                float* a = accS[kb][mt][nt];
                a[0] = __expf(a[0] - mx[mt][0]); a[1] = __expf(a[1] - mx[mt][0]);
                a[2] = __expf(a[2] - mx[mt][1]); a[3] = __expf(a[3] - mx[mt][1]);
                sum[mt][0] += a[0] + a[1]; sum[mt][1] += a[2] + a[3];
            }
    #pragma unroll
    for (int mt = 0; mt < 2; mt++)
        #pragma unroll
        for (int h = 0; h < 2; h++) {
            sum[mt][h] += __shfl_xor_sync(0xffffffffu, sum[mt][h], 1);
            sum[mt][h] += __shfl_xor_sync(0xffffffffu, sum[mt][h], 2);
        }
    float* rsum = (float*)(smem + OFF_RSUM);
    if ((lane & 3) == 0)
        #pragma unroll
        for (int mt = 0; mt < 2; mt++)
            #pragma unroll
            for (int h = 0; h < 2; h++)
                rsum[(mt * 16 + h * 8 + rq) * 4 + wid] = sum[mt][h];
    __syncthreads();
    float inv[2][2];
    #pragma unroll
    for (int mt = 0; mt < 2; mt++)
        #pragma unroll
        for (int h = 0; h < 2; h++) {
            const float* r4 = &rsum[(mt * 16 + h * 8 + rq) * 4];
            inv[mt][h] = 1.f / (r4[0] + r4[1] + r4[2] + r4[3]);
        }

    // ---- normalize + write attn ----
    float* attnB = attn + ((size_t)b * LN + qt * 32) * LN;
    #pragma unroll
    for (int kb = 0; kb < 4; kb++)
        #pragma unroll
        for (int mt = 0; mt < 2; mt++) {
            const int r0 = mt * 16 + rq, r1 = r0 + 8;
            #pragma unroll
            for (int nt = 0; nt < 4; nt++) {
                int c = kb * 128 + warp_n + nt * 8 + cq;
                float* a = accS[kb][mt][nt];
                a[0] *= inv[mt][0]; a[1] *= inv[mt][0];
                a[2] *= inv[mt][1]; a[3] *= inv[mt][1];
                *(float2*)(attnB + (size_t)r0 * LN + c) = make_float2(a[0], a[1]);
                *(float2*)(attnB + (size_t)r1 * LN + c) = make_float2(a[2], a[3]);
            }
        }

    // ---- PV over 4 chunks ----
    float accO[2][4][4];
    #pragma unroll
    for (int mt = 0; mt < 2; mt++)
        #pragma unroll
        for (int nt = 0; nt < 4; nt++)
            #pragma unroll
            for (int j = 0; j < 4; j++) accO[mt][nt][j] = 0.f;

    #pragma unroll
    for (int s = 0; s < 4; s++) {
        // P chunk s -> bf16 hi/lo smem (safe: all warps are past mma of chunk s-1)
        #pragma unroll
        for (int mt = 0; mt < 2; mt++) {
            const int r0 = mt * 16 + rq, r1 = r0 + 8;
            #pragma unroll
            for (int nt = 0; nt < 4; nt++) {
                int c = warp_n + nt * 8 + cq;
                const float* a = accS[s][mt][nt];
                float h0 = __bfloat162float(__float2bfloat16_rn(a[0]));
                float h1 = __bfloat162float(__float2bfloat16_rn(a[1]));
                float h2 = __bfloat162float(__float2bfloat16_rn(a[2]));
                float h3 = __bfloat162float(__float2bfloat16_rn(a[3]));
                uint32_t o0 = (uint32_t)(r0 * SSTR + c) * 2u;
                uint32_t o1 = (uint32_t)(r1 * SSTR + c) * 2u;
                *(uint32_t*)(smem + OFF_PHI + o0) = pack_bf2(a[0], a[1]);
                *(uint32_t*)(smem + OFF_PLO + o0) = pack_bf2(a[0] - h0, a[1] - h1);
                *(uint32_t*)(smem + OFF_PHI + o1) = pack_bf2(a[2], a[3]);
                *(uint32_t*)(smem + OFF_PLO + o1) = pack_bf2(a[2] - h2, a[3] - h3);
            }
        }
        CP_WAIT0();
        __syncthreads();
        mma_pv(sb, warp_n, lane, accO);
        __syncthreads();
        if (s < 3) {
            load_chunk(sb, g_Vhi, g_Vlo, bkv + (size_t)(s + 1) * 128 * DN, tid);
            CP_COMMIT();
        }
    }

    // ---- write out ----
    float* Og = out + ((size_t)b * LN + qt * 32) * DN;
    #pragma unroll
    for (int mt = 0; mt < 2; mt++) {
        const int r0 = mt * 16 + rq, r1 = r0 + 8;
        #pragma unroll
        for (int nt = 0; nt < 4; nt++) {
            int c = warp_n + nt * 8 + cq;
            *(float2*)(Og + (size_t)r0 * DN + c) = make_float2(accO[mt][nt][0], accO[mt][nt][1]);
            *(float2*)(Og + (size_t)r1 * DN + c) = make_float2(accO[mt][nt][2], accO[mt][nt][3]);
        }
    }
}

// ---------------------------------------------------------------------------
extern "C" void kernel_launch(void* const* d_in, const int* in_sizes, int n_in,
                              void* d_out, int out_size)
{
    const float* Q  = (const float*)d_in[0];
    const float* K  = (const float*)d_in[1];
    const float* V  = (const float*)d_in[2];
    const float* R  = (const float*)d_in[3];
    const float* M  = (const float*)d_in[4];

    float* out  = (float*)d_out;                       // [128,512,128]
    float* attn = out + (size_t)BHN * LN * DN;         // [128,512,512]

    static bool attr_set = false;
    if (!attr_set) {
        cudaFuncSetAttribute(fused_attn, cudaFuncAttributeMaxDynamicSharedMemorySize, SMEM_T);
        attr_set = true;
    }

    dim3 gprep((BHN * LN * DN) / 4 / 256, 2);          // (8192, 2)
    prep_kernel<<<gprep, 256>>>(K, V);

    rel_kernel<<<BHN * LQN, 256>>>(Q, R);              // 8192 blocks

    dim3 g(16, BHN);                                   // (q-tiles, batch-heads)
    fused_attn<<<g, 128, SMEM_T>>>(Q, M, attn, out);
}

// round 9
// speedup vs baseline: 2.2192x; 1.4523x over previous
#include <cuda_runtime.h>
#include <cuda_fp16.h>
#include <cstdint>

#define BHN 128
#define LN  512
#define DN  128
#define LQN 64
#define INV_SQRT_D 0.08838834764831843f

#define SSTR 136
#define OFF_QHI  0
#define OFF_QLO  8704
#define OFF_B    17408
#define OFF_PHI  52224
#define OFF_PLO  60928
#define OFF_MASK 69632
#define OFF_RMAX 71680
#define OFF_RSUM 72192
#define SMEM_T   72704

__device__ float g_Srel[(size_t)BHN * LQN * LQN];        // 2 MB
__device__ __half g_Kh[(size_t)BHN * LN * DN];           // 16 MB
__device__ __half g_Vh[(size_t)BHN * LN * DN];           // 16 MB

__device__ __forceinline__ uint32_t smem_u32(const void* p) {
    uint32_t a;
    asm("{ .reg .u64 t; cvta.to.shared.u64 t, %1; cvt.u32.u64 %0, t; }" : "=r"(a) : "l"(p));
    return a;
}
__device__ __forceinline__ uint32_t pack_h2(float a, float b) {
    __half2 h = __floats2half2_rn(a, b);    // .x = a (low half)
    return *(uint32_t*)&h;
}

#define LDSM_X4(r0, r1, r2, r3, addr)                                           \
    asm volatile("ldmatrix.sync.aligned.m8n8.x4.shared.b16 {%0,%1,%2,%3}, [%4];"\
                 : "=r"(r0), "=r"(r1), "=r"(r2), "=r"(r3) : "r"(addr))
#define LDSM_X4_T(r0, r1, r2, r3, addr)                                         \
    asm volatile("ldmatrix.sync.aligned.m8n8.x4.trans.shared.b16 {%0,%1,%2,%3}, [%4];"\
                 : "=r"(r0), "=r"(r1), "=r"(r2), "=r"(r3) : "r"(addr))
#define MMA_F16(c, a, b)                                                        \
    asm volatile("mma.sync.aligned.m16n8k16.row.col.f32.f16.f16.f32 "           \
                 "{%0,%1,%2,%3}, {%4,%5,%6,%7}, {%8,%9}, {%0,%1,%2,%3};"        \
                 : "+f"((c)[0]), "+f"((c)[1]), "+f"((c)[2]), "+f"((c)[3])       \
                 : "r"((a)[0]), "r"((a)[1]), "r"((a)[2]), "r"((a)[3]),          \
                   "r"((b)[0]), "r"((b)[1]))

#define CP16(dst, src)  asm volatile("cp.async.cg.shared.global [%0], [%1], 16;" :: "r"(dst), "l"(src))
#define CP_COMMIT()     asm volatile("cp.async.commit_group;" ::: "memory")
#define CP_WAIT0()      asm volatile("cp.async.wait_group 0;" ::: "memory")

// convert float4 (row r, cols 4*c4..) into hi/lo fp16 smem tiles (stride SSTR)
__device__ __forceinline__ void cvt_store(char* smem, int hi, int lo,
                                          int r, int c4, float4 v) {
    uint32_t off = (uint32_t)(r * SSTR + c4 * 4) * 2u;
    float hx = __half2float(__float2half_rn(v.x));
    float hy = __half2float(__float2half_rn(v.y));
    float hz = __half2float(__float2half_rn(v.z));
    float hw = __half2float(__float2half_rn(v.w));
    *(uint2*)(smem + hi + off) = make_uint2(pack_h2(v.x, v.y), pack_h2(v.z, v.w));
    *(uint2*)(smem + lo + off) = make_uint2(pack_h2(v.x - hx, v.y - hy),
                                            pack_h2(v.z - hz, v.w - hw));
}

// async-load one 128x128 fp16 chunk into the single B buffer (128 threads)
__device__ __forceinline__ void load_chunk(uint32_t sb, const __half* src,
                                           size_t base, int tid) {
    #pragma unroll
    for (int i = 0; i < 16; i++) {
        int idx = tid + 128 * i;         // 0..2047
        int r = idx >> 4, c8 = idx & 15;
        uint32_t doff = (uint32_t)(r * (SSTR * 2) + c8 * 16);
        CP16(sb + OFF_B + doff, src + base + (size_t)r * DN + c8 * 8);
    }
}

// QK chunk MMA: A = Q hi/lo (K-major), B = K chunk fp16 (K-major), m32 x n32, 2 chains
__device__ __forceinline__ void mma_qk(uint32_t sb, int warp_n, int lane,
                                       float acc[2][4][4]) {
    const int ar = lane & 15, acs = (lane >> 4) << 3;
    const int br = (lane & 7) | ((lane >> 4) << 3), bcs = ((lane >> 3) & 1) << 3;
    const uint32_t ab[2] = {sb + OFF_QHI, sb + OFF_QLO};
    #pragma unroll
    for (int ch = 0; ch < 2; ch++) {
        #pragma unroll
        for (int k16 = 0; k16 < 8; k16++) {
            const int kh = k16 * 16;
            uint32_t a[2][4];
            #pragma unroll
            for (int mt = 0; mt < 2; mt++)
                LDSM_X4(a[mt][0], a[mt][1], a[mt][2], a[mt][3],
                        ab[ch] + (uint32_t)((mt * 16 + ar) * SSTR + kh + acs) * 2u);
            uint32_t bf[4][2];
            #pragma unroll
            for (int p = 0; p < 2; p++) {
                uint32_t r0, r1, r2, r3;
                LDSM_X4(r0, r1, r2, r3,
                        sb + OFF_B + (uint32_t)((warp_n + p * 16 + br) * SSTR + kh + bcs) * 2u);
                bf[2*p][0] = r0; bf[2*p][1] = r1;
                bf[2*p+1][0] = r2; bf[2*p+1][1] = r3;
            }
            #pragma unroll
            for (int mt = 0; mt < 2; mt++)
                #pragma unroll
                for (int nt = 0; nt < 4; nt++) MMA_F16(acc[mt][nt], a[mt], bf[nt]);
        }
    }
}

// PV chunk MMA: A = P hi/lo (K-major), B = V chunk [k][d] via trans, m32 x n32, 2 chains
__device__ __forceinline__ void mma_pv(uint32_t sb, int warp_n, int lane,
                                       float acc[2][4][4]) {
    const int ar = lane & 15, acs = (lane >> 4) << 3;
    const int tkr = lane & 15, tnc = (lane >> 4) << 3;
    const uint32_t ab[2] = {sb + OFF_PHI, sb + OFF_PLO};
    #pragma unroll
    for (int ch = 0; ch < 2; ch++) {
        #pragma unroll
        for (int k16 = 0; k16 < 8; k16++) {
            const int kh = k16 * 16;
            uint32_t a[2][4];
            #pragma unroll
            for (int mt = 0; mt < 2; mt++)
                LDSM_X4(a[mt][0], a[mt][1], a[mt][2], a[mt][3],
                        ab[ch] + (uint32_t)((mt * 16 + ar) * SSTR + kh + acs) * 2u);
            uint32_t bf[4][2];
            #pragma unroll
            for (int p = 0; p < 2; p++) {
                uint32_t r0, r1, r2, r3;
                LDSM_X4_T(r0, r1, r2, r3,
                          sb + OFF_B + (uint32_t)((kh + tkr) * SSTR + warp_n + p * 16 + tnc) * 2u);
                bf[2*p][0] = r0; bf[2*p][1] = r1;
                bf[2*p+1][0] = r2; bf[2*p+1][1] = r3;
            }
            #pragma unroll
            for (int mt = 0; mt < 2; mt++)
                #pragma unroll
                for (int nt = 0; nt < 4; nt++) MMA_F16(acc[mt][nt], a[mt], bf[nt]);
        }
    }
}

// ---------------------------------------------------------------------------
// prep: K,V fp32 -> fp16 global scratch (single rounding)
// ---------------------------------------------------------------------------
__global__ __launch_bounds__(256) void prep_kernel(const float* __restrict__ K,
                                                   const float* __restrict__ V)
{
    size_t i4 = (size_t)blockIdx.x * 256 + threadIdx.x;
    const float* src = blockIdx.y ? V : K;
    __half* dst = blockIdx.y ? g_Vh : g_Kh;
    float4 v = ((const float4*)src)[i4];
    ((uint2*)dst)[i4] = make_uint2(pack_h2(v.x, v.y), pack_h2(v.z, v.w));
}

// ---------------------------------------------------------------------------
// rel: g_Srel[b,q',k'] = dot(R[b,q',k',:], Q[b,448+q',:])
// ---------------------------------------------------------------------------
__global__ __launch_bounds__(256) void rel_kernel(const float* __restrict__ Q,
                                                  const float* __restrict__ R)
{
    __shared__ float qrow[DN];
    const int b  = blockIdx.x >> 6;
    const int qp = blockIdx.x & 63;
    const int tid = threadIdx.x;

    if (tid < 32)
        ((float4*)qrow)[tid] =
            *(const float4*)(Q + ((size_t)b * LN + (LN - LQN) + qp) * DN + tid * 4);
    __syncthreads();

    const int w = tid >> 5, lane = tid & 31;
    const float4 qv = ((const float4*)qrow)[lane];

    #pragma unroll
    for (int i = 0; i < 8; i++) {
        int kp = w + i * 8;
        const float4* rp = (const float4*)(R + (((size_t)b * LQN + qp) * LQN + kp) * DN);
        float4 rv = rp[lane];
        float s = rv.x * qv.x + rv.y * qv.y + rv.z * qv.z + rv.w * qv.w;
        #pragma unroll
        for (int o = 16; o; o >>= 1) s += __shfl_xor_sync(0xffffffffu, s, o);
        if (lane == 0)
            g_Srel[((size_t)b * LQN + qp) * LQN + kp] = s;
    }
}

// ---------------------------------------------------------------------------
// fused: 128 threads, 4 warps, q-tile 32, warp tile m32 x n32, 2 CTAs/SM
// ---------------------------------------------------------------------------
__global__ __launch_bounds__(128, 2) void fused_attn(const float* __restrict__ Q,
                                                     const float* __restrict__ Mask,
                                                     float* __restrict__ attn,
                                                     float* __restrict__ out)
{
    extern __shared__ char smem[];
    const int tid = threadIdx.x, wid = tid >> 5, lane = tid & 31;
    const uint32_t sb = smem_u32(smem);
    const int b = blockIdx.y, qt = blockIdx.x;
    const size_t bkv = (size_t)b * LN * DN;

    // prologue: K chunk 0 in flight while we convert mask + Q
    load_chunk(sb, g_Kh, bkv, tid);
    CP_COMMIT();

    {
        float* sm = (float*)(smem + OFF_MASK);
        #pragma unroll
        for (int i = 0; i < 4; i++) {
            int idx = tid + 128 * i;
            float m = Mask[(size_t)b * LN + idx];
            sm[idx] = (m != 0.f) ? logf(1.f - m) : 0.f;
        }
    }
    {
        const float* Qg = Q + ((size_t)b * LN + qt * 32) * DN;
        #pragma unroll
        for (int i = 0; i < 8; i++) {
            int idx = tid + 128 * i;
            int r = idx >> 5, c4 = idx & 31;
            cvt_store(smem, OFF_QHI, OFF_QLO, r, c4, *(const float4*)(Qg + r * DN + c4 * 4));
        }
    }

    const int warp_n = wid * 32;
    const int rq = lane >> 2, cq = (lane & 3) * 2;

    float accS[4][2][4][4];
    #pragma unroll
    for (int kb = 0; kb < 4; kb++)
        #pragma unroll
        for (int mt = 0; mt < 2; mt++)
            #pragma unroll
            for (int nt = 0; nt < 4; nt++)
                #pragma unroll
                for (int j = 0; j < 4; j++) accS[kb][mt][nt][j] = 0.f;

    // ---- QK over 4 chunks; at s=3 start V chunk 0 (covers softmax latency) ----
    #pragma unroll
    for (int s = 0; s < 4; s++) {
        CP_WAIT0();
        __syncthreads();
        mma_qk(sb, warp_n, lane, accS[s]);
        __syncthreads();
        if (s < 3) load_chunk(sb, g_Kh, bkv + (size_t)(s + 1) * 128 * DN, tid);
        else       load_chunk(sb, g_Vh, bkv, tid);
        CP_COMMIT();
    }

    // ---- rel add: rows 448.. (qt>=14), cols 448.. (chunk 3, warps 2,3) ----
    if (qt >= 14 && wid >= 2) {
        const int qp0 = (qt - 14) * 32;
        #pragma unroll
        for (int mt = 0; mt < 2; mt++) {
            const int row0 = qp0 + mt * 16 + rq;
            #pragma unroll
            for (int nt = 0; nt < 4; nt++) {
                int kp = (wid - 2) * 32 + nt * 8 + cq;
                float2 s0 = *(const float2*)&g_Srel[((size_t)b * LQN + row0) * LQN + kp];
                float2 s1 = *(const float2*)&g_Srel[((size_t)b * LQN + row0 + 8) * LQN + kp];
                accS[3][mt][nt][0] += s0.x; accS[3][mt][nt][1] += s0.y;
                accS[3][mt][nt][2] += s1.x; accS[3][mt][nt][3] += s1.y;
            }
        }
    }

    // ---- scale + mask + row max ----
    const float* sm = (const float*)(smem + OFF_MASK);
    float mx[2][2];
    mx[0][0] = mx[0][1] = mx[1][0] = mx[1][1] = -1e30f;
    #pragma unroll
    for (int kb = 0; kb < 4; kb++)
        #pragma unroll
        for (int mt = 0; mt < 2; mt++)
            #pragma unroll
            for (int nt = 0; nt < 4; nt++) {
                int c = kb * 128 + warp_n + nt * 8 + cq;
                float ml0 = sm[c], ml1 = sm[c + 1];
                float* a = accS[kb][mt][nt];
                a[0] = fmaf(a[0], INV_SQRT_D, ml0);
                a[1] = fmaf(a[1], INV_SQRT_D, ml1);
                a[2] = fmaf(a[2], INV_SQRT_D, ml0);
                a[3] = fmaf(a[3], INV_SQRT_D, ml1);
                mx[mt][0] = fmaxf(mx[mt][0], fmaxf(a[0], a[1]));
                mx[mt][1] = fmaxf(mx[mt][1], fmaxf(a[2], a[3]));
            }
    #pragma unroll
    for (int mt = 0; mt < 2; mt++)
        #pragma unroll
        for (int h = 0; h < 2; h++) {
            mx[mt][h] = fmaxf(mx[mt][h], __shfl_xor_sync(0xffffffffu, mx[mt][h], 1));
            mx[mt][h] = fmaxf(mx[mt][h], __shfl_xor_sync(0xffffffffu, mx[mt][h], 2));
        }
    float* rmax = (float*)(smem + OFF_RMAX);
    if ((lane & 3) == 0)
        #pragma unroll
        for (int mt = 0; mt < 2; mt++)
            #pragma unroll
            for (int h = 0; h < 2; h++)
                rmax[(mt * 16 + h * 8 + rq) * 4 + wid] = mx[mt][h];
    __syncthreads();
    #pragma unroll
    for (int mt = 0; mt < 2; mt++)
        #pragma unroll
        for (int h = 0; h < 2; h++) {
            const float* r4 = &rmax[(mt * 16 + h * 8 + rq) * 4];
            mx[mt][h] = fmaxf(fmaxf(r4[0], r4[1]), fmaxf(r4[2], r4[3]));
        }

    // ---- exp + row sum ----
    float sum[2][2] = {{0.f, 0.f}, {0.f, 0.f}};
    #pragma unroll
    for (int kb = 0; kb < 4; kb++)
        #pragma unroll
        for (int mt = 0; mt < 2; mt++)
            #pragma unroll
            for (int nt = 0; nt < 4; nt++) {
                float* a = accS[kb][mt][nt];
                a[0] = __expf(a[0] - mx[mt][0]); a[1] = __expf(a[1] - mx[mt][0]);
                a[2] = __expf(a[2] - mx[mt][1]); a[3] = __expf(a[3] - mx[mt][1]);
                sum[mt][0] += a[0] + a[1]; sum[mt][1] += a[2] + a[3];
            }
    #pragma unroll
    for (int mt = 0; mt < 2; mt++)
        #pragma unroll
        for (int h = 0; h < 2; h++) {
            sum[mt][h] += __shfl_xor_sync(0xffffffffu, sum[mt][h], 1);
            sum[mt][h] += __shfl_xor_sync(0xffffffffu, sum[mt][h], 2);
        }
    float* rsum = (float*)(smem + OFF_RSUM);
    if ((lane & 3) == 0)
        #pragma unroll
        for (int mt = 0; mt < 2; mt++)
            #pragma unroll
            for (int h = 0; h < 2; h++)
                rsum[(mt * 16 + h * 8 + rq) * 4 + wid] = sum[mt][h];
    __syncthreads();
    float inv[2][2];
    #pragma unroll
    for (int mt = 0; mt < 2; mt++)
        #pragma unroll
        for (int h = 0; h < 2; h++) {
            const float* r4 = &rsum[(mt * 16 + h * 8 + rq) * 4];
            inv[mt][h] = 1.f / (r4[0] + r4[1] + r4[2] + r4[3]);
        }

    // ---- normalize + write attn ----
    float* attnB = attn + ((size_t)b * LN + qt * 32) * LN;
    #pragma unroll
    for (int kb = 0; kb < 4; kb++)
        #pragma unroll
        for (int mt = 0; mt < 2; mt++) {
            const int r0 = mt * 16 + rq, r1 = r0 + 8;
            #pragma unroll
            for (int nt = 0; nt < 4; nt++) {
                int c = kb * 128 + warp_n + nt * 8 + cq;
                float* a = accS[kb][mt][nt];
                a[0] *= inv[mt][0]; a[1] *= inv[mt][0];
                a[2] *= inv[mt][1]; a[3] *= inv[mt][1];
                *(float2*)(attnB + (size_t)r0 * LN + c) = make_float2(a[0], a[1]);
                *(float2*)(attnB + (size_t)r1 * LN + c) = make_float2(a[2], a[3]);
            }
        }

    // ---- PV over 4 chunks ----
    float accO[2][4][4];
    #pragma unroll
    for (int mt = 0; mt < 2; mt++)
        #pragma unroll
        for (int nt = 0; nt < 4; nt++)
            #pragma unroll
            for (int j = 0; j < 4; j++) accO[mt][nt][j] = 0.f;

    #pragma unroll
    for (int s = 0; s < 4; s++) {
        // P chunk s -> fp16 hi/lo smem (safe: all warps are past mma of chunk s-1)
        #pragma unroll
        for (int mt = 0; mt < 2; mt++) {
            const int r0 = mt * 16 + rq, r1 = r0 + 8;
            #pragma unroll
            for (int nt = 0; nt < 4; nt++) {
                int c = warp_n + nt * 8 + cq;
                const float* a = accS[s][mt][nt];
                float h0 = __half2float(__float2half_rn(a[0]));
                float h1 = __half2float(__float2half_rn(a[1]));
                float h2 = __half2float(__float2half_rn(a[2]));
                float h3 = __half2float(__float2half_rn(a[3]));
                uint32_t o0 = (uint32_t)(r0 * SSTR + c) * 2u;
                uint32_t o1 = (uint32_t)(r1 * SSTR + c) * 2u;
                *(uint32_t*)(smem + OFF_PHI + o0) = pack_h2(a[0], a[1]);
                *(uint32_t*)(smem + OFF_PLO + o0) = pack_h2(a[0] - h0, a[1] - h1);
                *(uint32_t*)(smem + OFF_PHI + o1) = pack_h2(a[2], a[3]);
                *(uint32_t*)(smem + OFF_PLO + o1) = pack_h2(a[2] - h2, a[3] - h3);
            }
        }
        CP_WAIT0();
        __syncthreads();
        mma_pv(sb, warp_n, lane, accO);
        __syncthreads();
        if (s < 3) {
            load_chunk(sb, g_Vh, bkv + (size_t)(s + 1) * 128 * DN, tid);
            CP_COMMIT();
        }
    }

    // ---- write out ----
    float* Og = out + ((size_t)b * LN + qt * 32) * DN;
    #pragma unroll
    for (int mt = 0; mt < 2; mt++) {
        const int r0 = mt * 16 + rq, r1 = r0 + 8;
        #pragma unroll
        for (int nt = 0; nt < 4; nt++) {
            int c = warp_n + nt * 8 + cq;
            *(float2*)(Og + (size_t)r0 * DN + c) = make_float2(accO[mt][nt][0], accO[mt][nt][1]);
            *(float2*)(Og + (size_t)r1 * DN + c) = make_float2(accO[mt][nt][2], accO[mt][nt][3]);
        }
    }
}

// ---------------------------------------------------------------------------
extern "C" void kernel_launch(void* const* d_in, const int* in_sizes, int n_in,
                              void* d_out, int out_size)
{
    const float* Q  = (const float*)d_in[0];
    const float* K  = (const float*)d_in[1];
    const float* V  = (const float*)d_in[2];
    const float* R  = (const float*)d_in[3];
    const float* M  = (const float*)d_in[4];

    float* out  = (float*)d_out;                       // [128,512,128]
    float* attn = out + (size_t)BHN * LN * DN;         // [128,512,512]

    static bool attr_set = false;
    if (!attr_set) {
        cudaFuncSetAttribute(fused_attn, cudaFuncAttributeMaxDynamicSharedMemorySize, SMEM_T);
        attr_set = true;
    }

    dim3 gprep((BHN * LN * DN) / 4 / 256, 2);          // (8192, 2)
    prep_kernel<<<gprep, 256>>>(K, V);

    rel_kernel<<<BHN * LQN, 256>>>(Q, R);              // 8192 blocks

    dim3 g(16, BHN);                                   // (q-tiles, batch-heads)
    fused_attn<<<g, 128, SMEM_T>>>(Q, M, attn, out);
}

// round 10
// speedup vs baseline: 2.2651x; 1.0207x over previous
#include <cuda_runtime.h>
#include <cuda_fp16.h>
#include <cstdint>

#define BHN 128
#define LN  512
#define DN  128
#define LQN 64
#define INV_SQRT_D 0.08838834764831843f

#define SSTR 136
#define OFF_QHI  0
#define OFF_QLO  8704
#define OFF_B0   17408
#define OFF_B1   52224
#define OFF_PHI  87040
#define OFF_PLO  95744
#define OFF_MASK 104448
#define OFF_RMAX 106496
#define OFF_RSUM 107008
#define SMEM_T   107520

__device__ float g_Srel[(size_t)BHN * LQN * LQN];        // 2 MB
__device__ __half g_Kh[(size_t)BHN * LN * DN];           // 16 MB
__device__ __half g_Vh[(size_t)BHN * LN * DN];           // 16 MB

__device__ __forceinline__ uint32_t smem_u32(const void* p) {
    uint32_t a;
    asm("{ .reg .u64 t; cvta.to.shared.u64 t, %1; cvt.u32.u64 %0, t; }" : "=r"(a) : "l"(p));
    return a;
}
__device__ __forceinline__ uint32_t pack_h2(float a, float b) {
    __half2 h = __floats2half2_rn(a, b);    // .x = a (low half)
    return *(uint32_t*)&h;
}

#define LDSM_X4(r0, r1, r2, r3, addr)                                           \
    asm volatile("ldmatrix.sync.aligned.m8n8.x4.shared.b16 {%0,%1,%2,%3}, [%4];"\
                 : "=r"(r0), "=r"(r1), "=r"(r2), "=r"(r3) : "r"(addr))
#define LDSM_X4_T(r0, r1, r2, r3, addr)                                         \
    asm volatile("ldmatrix.sync.aligned.m8n8.x4.trans.shared.b16 {%0,%1,%2,%3}, [%4];"\
                 : "=r"(r0), "=r"(r1), "=r"(r2), "=r"(r3) : "r"(addr))
#define MMA_F16(c, a, b)                                                        \
    asm volatile("mma.sync.aligned.m16n8k16.row.col.f32.f16.f16.f32 "           \
                 "{%0,%1,%2,%3}, {%4,%5,%6,%7}, {%8,%9}, {%0,%1,%2,%3};"        \
                 : "+f"((c)[0]), "+f"((c)[1]), "+f"((c)[2]), "+f"((c)[3])       \
                 : "r"((a)[0]), "r"((a)[1]), "r"((a)[2]), "r"((a)[3]),          \
                   "r"((b)[0]), "r"((b)[1]))

#define CP16(dst, src)  asm volatile("cp.async.cg.shared.global [%0], [%1], 16;" :: "r"(dst), "l"(src))
#define CP_COMMIT()     asm volatile("cp.async.commit_group;" ::: "memory")
#define CP_WAIT1()      asm volatile("cp.async.wait_group 1;" ::: "memory")
#define CP_WAIT0()      asm volatile("cp.async.wait_group 0;" ::: "memory")

// convert float4 (row r, cols 4*c4..) into hi/lo fp16 smem tiles (stride SSTR)
__device__ __forceinline__ void cvt_store(char* smem, int hi, int lo,
                                          int r, int c4, float4 v) {
    uint32_t off = (uint32_t)(r * SSTR + c4 * 4) * 2u;
    float hx = __half2float(__float2half_rn(v.x));
    float hy = __half2float(__float2half_rn(v.y));
    float hz = __half2float(__float2half_rn(v.z));
    float hw = __half2float(__float2half_rn(v.w));
    *(uint2*)(smem + hi + off) = make_uint2(pack_h2(v.x, v.y), pack_h2(v.z, v.w));
    *(uint2*)(smem + lo + off) = make_uint2(pack_h2(v.x - hx, v.y - hy),
                                            pack_h2(v.z - hz, v.w - hw));
}

// async-load one 128x128 fp16 chunk into buffer at bufoff (128 threads)
__device__ __forceinline__ void load_chunk(uint32_t sb, uint32_t bufoff,
                                           const __half* src, size_t base, int tid) {
    #pragma unroll
    for (int i = 0; i < 16; i++) {
        int idx = tid + 128 * i;         // 0..2047
        int r = idx >> 4, c8 = idx & 15;
        uint32_t doff = (uint32_t)(r * (SSTR * 2) + c8 * 16);
        CP16(sb + bufoff + doff, src + base + (size_t)r * DN + c8 * 8);
    }
}

// QK chunk MMA: A = Q hi/lo (K-major), B = chunk at bufoff (K-major), m32 x n32
__device__ __forceinline__ void mma_qk(uint32_t sb, uint32_t bufoff, int warp_n,
                                       int lane, float acc[2][4][4]) {
    const int ar = lane & 15, acs = (lane >> 4) << 3;
    const int br = (lane & 7) | ((lane >> 4) << 3), bcs = ((lane >> 3) & 1) << 3;
    const uint32_t ab[2] = {sb + OFF_QHI, sb + OFF_QLO};
    #pragma unroll
    for (int ch = 0; ch < 2; ch++) {
        #pragma unroll
        for (int k16 = 0; k16 < 8; k16++) {
            const int kh = k16 * 16;
            uint32_t a[2][4];
            #pragma unroll
            for (int mt = 0; mt < 2; mt++)
                LDSM_X4(a[mt][0], a[mt][1], a[mt][2], a[mt][3],
                        ab[ch] + (uint32_t)((mt * 16 + ar) * SSTR + kh + acs) * 2u);
            uint32_t bf[4][2];
            #pragma unroll
            for (int p = 0; p < 2; p++) {
                uint32_t r0, r1, r2, r3;
                LDSM_X4(r0, r1, r2, r3,
                        sb + bufoff + (uint32_t)((warp_n + p * 16 + br) * SSTR + kh + bcs) * 2u);
                bf[2*p][0] = r0; bf[2*p][1] = r1;
                bf[2*p+1][0] = r2; bf[2*p+1][1] = r3;
            }
            #pragma unroll
            for (int mt = 0; mt < 2; mt++)
                #pragma unroll
                for (int nt = 0; nt < 4; nt++) MMA_F16(acc[mt][nt], a[mt], bf[nt]);
        }
    }
}

// PV chunk MMA: A = P hi/lo (K-major), B = chunk at bufoff [k][d] via trans
__device__ __forceinline__ void mma_pv(uint32_t sb, uint32_t bufoff, int warp_n,
                                       int lane, float acc[2][4][4]) {
    const int ar = lane & 15, acs = (lane >> 4) << 3;
    const int tkr = lane & 15, tnc = (lane >> 4) << 3;
    const uint32_t ab[2] = {sb + OFF_PHI, sb + OFF_PLO};
    #pragma unroll
    for (int ch = 0; ch < 2; ch++) {
        #pragma unroll
        for (int k16 = 0; k16 < 8; k16++) {
            const int kh = k16 * 16;
            uint32_t a[2][4];
            #pragma unroll
            for (int mt = 0; mt < 2; mt++)
                LDSM_X4(a[mt][0], a[mt][1], a[mt][2], a[mt][3],
                        ab[ch] + (uint32_t)((mt * 16 + ar) * SSTR + kh + acs) * 2u);
            uint32_t bf[4][2];
            #pragma unroll
            for (int p = 0; p < 2; p++) {
                uint32_t r0, r1, r2, r3;
                LDSM_X4_T(r0, r1, r2, r3,
                          sb + bufoff + (uint32_t)((kh + tkr) * SSTR + warp_n + p * 16 + tnc) * 2u);
                bf[2*p][0] = r0; bf[2*p][1] = r1;
                bf[2*p+1][0] = r2; bf[2*p+1][1] = r3;
            }
            #pragma unroll
            for (int mt = 0; mt < 2; mt++)
                #pragma unroll
                for (int nt = 0; nt < 4; nt++) MMA_F16(acc[mt][nt], a[mt], bf[nt]);
        }
    }
}

// ---------------------------------------------------------------------------
// prep: K,V fp32 -> fp16 global scratch (single rounding)
// ---------------------------------------------------------------------------
__global__ __launch_bounds__(256) void prep_kernel(const float* __restrict__ K,
                                                   const float* __restrict__ V)
{
    size_t i4 = (size_t)blockIdx.x * 256 + threadIdx.x;
    const float* src = blockIdx.y ? V : K;
    __half* dst = blockIdx.y ? g_Vh : g_Kh;
    float4 v = ((const float4*)src)[i4];
    ((uint2*)dst)[i4] = make_uint2(pack_h2(v.x, v.y), pack_h2(v.z, v.w));
}

// ---------------------------------------------------------------------------
// rel: g_Srel[b,q',k'] = dot(R[b,q',k',:], Q[b,448+q',:])
// ---------------------------------------------------------------------------
__global__ __launch_bounds__(256) void rel_kernel(const float* __restrict__ Q,
                                                  const float* __restrict__ R)
{
    __shared__ float qrow[DN];
    const int b  = blockIdx.x >> 6;
    const int qp = blockIdx.x & 63;
    const int tid = threadIdx.x;

    if (tid < 32)
        ((float4*)qrow)[tid] =
            *(const float4*)(Q + ((size_t)b * LN + (LN - LQN) + qp) * DN + tid * 4);
    __syncthreads();

    const int w = tid >> 5, lane = tid & 31;
    const float4 qv = ((const float4*)qrow)[lane];

    #pragma unroll
    for (int i = 0; i < 8; i++) {
        int kp = w + i * 8;
        const float4* rp = (const float4*)(R + (((size_t)b * LQN + qp) * LQN + kp) * DN);
        float4 rv = rp[lane];
        float s = rv.x * qv.x + rv.y * qv.y + rv.z * qv.z + rv.w * qv.w;
        #pragma unroll
        for (int o = 16; o; o >>= 1) s += __shfl_xor_sync(0xffffffffu, s, o);
        if (lane == 0)
            g_Srel[((size_t)b * LQN + qp) * LQN + kp] = s;
    }
}

// ---------------------------------------------------------------------------
// fused: 128 threads, 4 warps, q-tile 32, m32 x n32 warp tiles, double-buffered B
// ---------------------------------------------------------------------------
__global__ __launch_bounds__(128, 2) void fused_attn(const float* __restrict__ Q,
                                                     const float* __restrict__ Mask,
                                                     float* __restrict__ attn,
                                                     float* __restrict__ out)
{
    extern __shared__ char smem[];
    const int tid = threadIdx.x, wid = tid >> 5, lane = tid & 31;
    const uint32_t sb = smem_u32(smem);
    const int b = blockIdx.y, qt = blockIdx.x;
    const size_t bkv = (size_t)b * LN * DN;
    const uint32_t buf[2] = {OFF_B0, OFF_B1};

    // prologue: K0 -> buf0, K1 -> buf1
    load_chunk(sb, OFF_B0, g_Kh, bkv, tid);
    CP_COMMIT();
    load_chunk(sb, OFF_B1, g_Kh, bkv + 128 * DN, tid);
    CP_COMMIT();

    {
        float* sm = (float*)(smem + OFF_MASK);
        #pragma unroll
        for (int i = 0; i < 4; i++) {
            int idx = tid + 128 * i;
            float m = Mask[(size_t)b * LN + idx];
            sm[idx] = (m != 0.f) ? logf(1.f - m) : 0.f;
        }
    }
    {
        const float* Qg = Q + ((size_t)b * LN + qt * 32) * DN;
        #pragma unroll
        for (int i = 0; i < 8; i++) {
            int idx = tid + 128 * i;
            int r = idx >> 5, c4 = idx & 31;
            cvt_store(smem, OFF_QHI, OFF_QLO, r, c4, *(const float4*)(Qg + r * DN + c4 * 4));
        }
    }

    const int warp_n = wid * 32;
    const int rq = lane >> 2, cq = (lane & 3) * 2;

    float accS[4][2][4][4];
    #pragma unroll
    for (int kb = 0; kb < 4; kb++)
        #pragma unroll
        for (int mt = 0; mt < 2; mt++)
            #pragma unroll
            for (int nt = 0; nt < 4; nt++)
                #pragma unroll
                for (int j = 0; j < 4; j++) accS[kb][mt][nt][j] = 0.f;

    // ---- QK: stage s computes chunk s from buf[s&1], prefetches s+2 (K2,K3,V0,V1) ----
    #pragma unroll
    for (int s = 0; s < 4; s++) {
        CP_WAIT1();
        __syncthreads();
        mma_qk(sb, buf[s & 1], warp_n, lane, accS[s]);
        __syncthreads();
        if (s < 2) load_chunk(sb, buf[s & 1], g_Kh, bkv + (size_t)(s + 2) * 128 * DN, tid);
        else       load_chunk(sb, buf[s & 1], g_Vh, bkv + (size_t)(s - 2) * 128 * DN, tid);
        CP_COMMIT();
    }

    // ---- rel add: rows 448.. (qt>=14), cols 448.. (chunk 3, warps 2,3) ----
    if (qt >= 14 && wid >= 2) {
        const int qp0 = (qt - 14) * 32;
        #pragma unroll
        for (int mt = 0; mt < 2; mt++) {
            const int row0 = qp0 + mt * 16 + rq;
            #pragma unroll
            for (int nt = 0; nt < 4; nt++) {
                int kp = (wid - 2) * 32 + nt * 8 + cq;
                float2 s0 = *(const float2*)&g_Srel[((size_t)b * LQN + row0) * LQN + kp];
                float2 s1 = *(const float2*)&g_Srel[((size_t)b * LQN + row0 + 8) * LQN + kp];
                accS[3][mt][nt][0] += s0.x; accS[3][mt][nt][1] += s0.y;
                accS[3][mt][nt][2] += s1.x; accS[3][mt][nt][3] += s1.y;
            }
        }
    }

    // ---- scale + mask + row max ----
    const float* sm = (const float*)(smem + OFF_MASK);
    float mx[2][2];
    mx[0][0] = mx[0][1] = mx[1][0] = mx[1][1] = -1e30f;
    #pragma unroll
    for (int kb = 0; kb < 4; kb++)
        #pragma unroll
        for (int mt = 0; mt < 2; mt++)
            #pragma unroll
            for (int nt = 0; nt < 4; nt++) {
                int c = kb * 128 + warp_n + nt * 8 + cq;
                float ml0 = sm[c], ml1 = sm[c + 1];
                float* a = accS[kb][mt][nt];
                a[0] = fmaf(a[0], INV_SQRT_D, ml0);
                a[1] = fmaf(a[1], INV_SQRT_D, ml1);
                a[2] = fmaf(a[2], INV_SQRT_D, ml0);
                a[3] = fmaf(a[3], INV_SQRT_D, ml1);
                mx[mt][0] = fmaxf(mx[mt][0], fmaxf(a[0], a[1]));
                mx[mt][1] = fmaxf(mx[mt][1], fmaxf(a[2], a[3]));
            }
    #pragma unroll
    for (int mt = 0; mt < 2; mt++)
        #pragma unroll
        for (int h = 0; h < 2; h++) {
            mx[mt][h] = fmaxf(mx[mt][h], __shfl_xor_sync(0xffffffffu, mx[mt][h], 1));
            mx[mt][h] = fmaxf(mx[mt][h], __shfl_xor_sync(0xffffffffu, mx[mt][h], 2));
        }
    float* rmax = (float*)(smem + OFF_RMAX);
    if ((lane & 3) == 0)
        #pragma unroll
        for (int mt = 0; mt < 2; mt++)
            #pragma unroll
            for (int h = 0; h < 2; h++)
                rmax[(mt * 16 + h * 8 + rq) * 4 + wid] = mx[mt][h];
    __syncthreads();
    #pragma unroll
    for (int mt = 0; mt < 2; mt++)
        #pragma unroll
        for (int h = 0; h < 2; h++) {
            const float* r4 = &rmax[(mt * 16 + h * 8 + rq) * 4];
            mx[mt][h] = fmaxf(fmaxf(r4[0], r4[1]), fmaxf(r4[2], r4[3]));
        }

    // ---- exp + row sum ----
    float sum[2][2] = {{0.f, 0.f}, {0.f, 0.f}};
    #pragma unroll
    for (int kb = 0; kb < 4; kb++)
        #pragma unroll
        for (int mt = 0; mt < 2; mt++)
            #pragma unroll
            for (int nt = 0; nt < 4; nt++) {
                float* a = accS[kb][mt][nt];
                a[0] = __expf(a[0] - mx[mt][0]); a[1] = __expf(a[1] - mx[mt][0]);
                a[2] = __expf(a[2] - mx[mt][1]); a[3] = __expf(a[3] - mx[mt][1]);
                sum[mt][0] += a[0] + a[1]; sum[mt][1] += a[2] + a[3];
            }
    #pragma unroll
    for (int mt = 0; mt < 2; mt++)
        #pragma unroll
        for (int h = 0; h < 2; h++) {
            sum[mt][h] += __shfl_xor_sync(0xffffffffu, sum[mt][h], 1);
            sum[mt][h] += __shfl_xor_sync(0xffffffffu, sum[mt][h], 2);
        }
    float* rsum = (float*)(smem + OFF_RSUM);
    if ((lane & 3) == 0)
        #pragma unroll
        for (int mt = 0; mt < 2; mt++)
            #pragma unroll
            for (int h = 0; h < 2; h++)
                rsum[(mt * 16 + h * 8 + rq) * 4 + wid] = sum[mt][h];
    __syncthreads();
    float inv[2][2];
    #pragma unroll
    for (int mt = 0; mt < 2; mt++)
        #pragma unroll
        for (int h = 0; h < 2; h++) {
            const float* r4 = &rsum[(mt * 16 + h * 8 + rq) * 4];
            inv[mt][h] = 1.f / (r4[0] + r4[1] + r4[2] + r4[3]);
        }

    // ---- normalize + write attn (streaming stores: single-use data) ----
    float* attnB = attn + ((size_t)b * LN + qt * 32) * LN;
    #pragma unroll
    for (int kb = 0; kb < 4; kb++)
        #pragma unroll
        for (int mt = 0; mt < 2; mt++) {
            const int r0 = mt * 16 + rq, r1 = r0 + 8;
            #pragma unroll
            for (int nt = 0; nt < 4; nt++) {
                int c = kb * 128 + warp_n + nt * 8 + cq;
                float* a = accS[kb][mt][nt];
                a[0] *= inv[mt][0]; a[1] *= inv[mt][0];
                a[2] *= inv[mt][1]; a[3] *= inv[mt][1];
                __stcs((float2*)(attnB + (size_t)r0 * LN + c), make_float2(a[0], a[1]));
                __stcs((float2*)(attnB + (size_t)r1 * LN + c), make_float2(a[2], a[3]));
            }
        }

    // ---- PV: stage s computes chunk s from buf[s&1], prefetches V s+2 ----
    float accO[2][4][4];
    #pragma unroll
    for (int mt = 0; mt < 2; mt++)
        #pragma unroll
        for (int nt = 0; nt < 4; nt++)
            #pragma unroll
            for (int j = 0; j < 4; j++) accO[mt][nt][j] = 0.f;

    #pragma unroll
    for (int s = 0; s < 4; s++) {
        // P chunk s -> fp16 hi/lo smem
        #pragma unroll
        for (int mt = 0; mt < 2; mt++) {
            const int r0 = mt * 16 + rq, r1 = r0 + 8;
            #pragma unroll
            for (int nt = 0; nt < 4; nt++) {
                int c = warp_n + nt * 8 + cq;
                const float* a = accS[s][mt][nt];
                float h0 = __half2float(__float2half_rn(a[0]));
                float h1 = __half2float(__float2half_rn(a[1]));
                float h2 = __half2float(__float2half_rn(a[2]));
                float h3 = __half2float(__float2half_rn(a[3]));
                uint32_t o0 = (uint32_t)(r0 * SSTR + c) * 2u;
                uint32_t o1 = (uint32_t)(r1 * SSTR + c) * 2u;
                *(uint32_t*)(smem + OFF_PHI + o0) = pack_h2(a[0], a[1]);
                *(uint32_t*)(smem + OFF_PLO + o0) = pack_h2(a[0] - h0, a[1] - h1);
                *(uint32_t*)(smem + OFF_PHI + o1) = pack_h2(a[2], a[3]);
                *(uint32_t*)(smem + OFF_PLO + o1) = pack_h2(a[2] - h2, a[3] - h3);
            }
        }
        if (s < 3) { CP_WAIT1(); } else { CP_WAIT0(); }
        __syncthreads();
        mma_pv(sb, buf[s & 1], warp_n, lane, accO);
        __syncthreads();
        if (s < 2) {
            load_chunk(sb, buf[s & 1], g_Vh, bkv + (size_t)(s + 2) * 128 * DN, tid);
            CP_COMMIT();
        }
    }

    // ---- write out ----
    float* Og = out + ((size_t)b * LN + qt * 32) * DN;
    #pragma unroll
    for (int mt = 0; mt < 2; mt++) {
        const int r0 = mt * 16 + rq, r1 = r0 + 8;
        #pragma unroll
        for (int nt = 0; nt < 4; nt++) {
            int c = warp_n + nt * 8 + cq;
            __stcs((float2*)(Og + (size_t)r0 * DN + c), make_float2(accO[mt][nt][0], accO[mt][nt][1]));
            __stcs((float2*)(Og + (size_t)r1 * DN + c), make_float2(accO[mt][nt][2], accO[mt][nt][3]));
        }
    }
}

// ---------------------------------------------------------------------------
extern "C" void kernel_launch(void* const* d_in, const int* in_sizes, int n_in,
                              void* d_out, int out_size)
{
    const float* Q  = (const float*)d_in[0];
    const float* K  = (const float*)d_in[1];
    const float* V  = (const float*)d_in[2];
    const float* R  = (const float*)d_in[3];
    const float* M  = (const float*)d_in[4];

    float* out  = (float*)d_out;                       // [128,512,128]
    float* attn = out + (size_t)BHN * LN * DN;         // [128,512,512]

    static bool attr_set = false;
    if (!attr_set) {
        cudaFuncSetAttribute(fused_attn, cudaFuncAttributeMaxDynamicSharedMemorySize, SMEM_T);
        attr_set = true;
    }

    dim3 gprep((BHN * LN * DN) / 4 / 256, 2);          // (8192, 2)
    prep_kernel<<<gprep, 256>>>(K, V);

    rel_kernel<<<BHN * LQN, 256>>>(Q, R);              // 8192 blocks

    dim3 g(16, BHN);                                   // (q-tiles, batch-heads)
    fused_attn<<<g, 128, SMEM_T>>>(Q, M, attn, out);
}